// round 10
// baseline (speedup 1.0000x reference)
#include <cuda_runtime.h>
#include <cuda_fp16.h>
#include <cstdint>

#define B_ 32
#define S_ 4096
#define D_ 512
#define H_ 512

// ---------------- device scratch ----------------
__device__ float  g_add[B_ * H_];
__device__ __half g_Wh[H_ * D_];
__device__ float  g_att[B_ * S_];
__device__ float  g_alpha[B_ * S_];
__device__ float  g_cbar_part[B_ * 16 * D_];
__device__ float  g_cbar[B_ * D_];
__device__ int    g_idx[B_ * S_];
__device__ int    g_cnt[B_];

// ---------------- helpers ----------------
__device__ __forceinline__ uint32_t smem_u32(const void* p) {
    uint32_t a;
    asm("{ .reg .u64 t; cvta.to.shared.u64 t, %1; cvt.u32.u64 %0, t; }" : "=r"(a) : "l"(p));
    return a;
}

__device__ __forceinline__ uint32_t h2_as_u32(__half2 h) {
    union { __half2 h; uint32_t u; } cvt;
    cvt.h = h;
    return cvt.u;
}

#define LDSM4(r0, r1, r2, r3, addr) \
    asm volatile("ldmatrix.sync.aligned.m8n8.x4.shared.b16 {%0,%1,%2,%3}, [%4];" \
                 : "=r"(r0), "=r"(r1), "=r"(r2), "=r"(r3) : "r"(addr))

#define MMAF16(d, a, b0, b1) \
    asm volatile("mma.sync.aligned.m16n8k16.row.col.f32.f16.f16.f32 " \
                 "{%0,%1,%2,%3}, {%4,%5,%6,%7}, {%8,%9}, {%0,%1,%2,%3};" \
                 : "+f"((d)[0]), "+f"((d)[1]), "+f"((d)[2]), "+f"((d)[3]) \
                 : "r"((a)[0]), "r"((a)[1]), "r"((a)[2]), "r"((a)[3]), "r"(b0), "r"(b1))

#define CP_ASYNC16(dst, src) \
    asm volatile("cp.async.cg.shared.global [%0], [%1], 16;" :: "r"(dst), "l"(src))
#define CP_COMMIT() asm volatile("cp.async.commit_group;")
#define CP_WAIT0()  asm volatile("cp.async.wait_group 0;")

// Accurate tanh with NO MUFU. abs err ~1e-5.
__device__ __forceinline__ float fast_tanh(float x) {
    float ax = fabsf(x);
    float z  = fminf(ax * 2.8853900817779268f, 30.0f);
    float zf = z + 12582912.0f;
    int   ni = __float_as_int(zf) - 0x4B400000;
    float fr = z - (zf - 12582912.0f);
    float p  = 1.3333558146e-3f;
    p = fmaf(p, fr, 9.6181291076e-3f);
    p = fmaf(p, fr, 5.5504108665e-2f);
    p = fmaf(p, fr, 2.4022650696e-1f);
    p = fmaf(p, fr, 6.9314718056e-1f);
    p = fmaf(p, fr, 1.0f);
    float u = __int_as_float((ni + 127) << 23) * p;
    float d = u + 1.0f;
    float r = __int_as_float(0x7EF311C3u - __float_as_uint(d));
    r = r * fmaf(-d, r, 2.0f);
    r = r * fmaf(-d, r, 2.0f);
    float t = fmaf(-2.0f, r, 1.0f);
    return copysignf(t, x);
}

// ---------------- K0a: W_ctx -> fp16 ----------------
__global__ void k0a_split(const float* __restrict__ W) {
    int i = blockIdx.x * 256 + threadIdx.x;
    if (i < H_ * D_) g_Wh[i] = __float2half_rn(W[i]);
}

// ---------------- K0b ----------------
__global__ void __launch_bounds__(256) k0b_add(const float* __restrict__ input,
                                               const float* __restrict__ W_in,
                                               const float* __restrict__ b_in,
                                               const float* __restrict__ b_ctx) {
    int gw = blockIdx.x * 8 + (threadIdx.x >> 5);
    int lane = threadIdx.x & 31;
    int b = gw >> 9, h = gw & 511;
    const float* w = W_in + (size_t)h * D_;
    const float* in = input + (size_t)b * D_;
    float s = 0.f;
    #pragma unroll
    for (int i = 0; i < 16; i++) {
        int d = lane + 32 * i;
        s = fmaf(w[d], in[d], s);
    }
    #pragma unroll
    for (int o = 16; o; o >>= 1) s += __shfl_xor_sync(0xffffffffu, s, o);
    if (lane == 0) g_add[b * H_ + h] = s + b_in[h] + b_ctx[h];
}

// ---------------- K0c ----------------
__global__ void __launch_bounds__(256) k0c_compact(const int* __restrict__ mask) {
    int b = blockIdx.x, tid = threadIdx.x, lane = tid & 31;
    for (int i = tid; i < S_; i += 256) g_att[b * S_ + i] = 0.f;
    if (tid < 32) {
        int base = 0;
        for (int s0 = 0; s0 < S_; s0 += 32) {
            int s = s0 + lane;
            bool keep = (mask[b * S_ + s] == 0);
            unsigned bal = __ballot_sync(0xffffffffu, keep);
            int rank = __popc(bal & ((1u << lane) - 1u));
            if (keep) g_idx[b * S_ + base + rank] = s;
            base += __popc(bal);
        }
        if (lane == 0) g_cnt[b] = base;
    }
}

// ---------------- K1: fp16 2-term (A hi/lo) GEMM, 256 threads, 2 CTAs/SM ----------------
// 8 warps (2s x 4h), warp tile 32x64. CTA tile M=64, N=256, K=512 (8 x 64).
#define MS 64
#define NH 256
// smem (bytes): A hi 2 stages x 9216, A lo 2 x 9216, W 2 x 36864
#define SA_HI 0
#define SA_LO 18432
#define SW0   36864
#define SADD  110592
#define SVV   111616
#define SATT  112640
#define SIDX  112896
#define SMEM_K1 113152

// store 8 consecutive fp32 as fp16 hi (16B) + fp16 lo residual (16B)
__device__ __forceinline__ void store_a_pair(char* sm, int st, int row, int segpair,
                                             float4 x, float4 y) {
    __half hx0 = __float2half_rn(x.x), hx1 = __float2half_rn(x.y);
    __half hx2 = __float2half_rn(x.z), hx3 = __float2half_rn(x.w);
    __half hy0 = __float2half_rn(y.x), hy1 = __float2half_rn(y.y);
    __half hy2 = __float2half_rn(y.z), hy3 = __float2half_rn(y.w);
    uint4 vh, vl;
    vh.x = h2_as_u32(__halves2half2(hx0, hx1));
    vh.y = h2_as_u32(__halves2half2(hx2, hx3));
    vh.z = h2_as_u32(__halves2half2(hy0, hy1));
    vh.w = h2_as_u32(__halves2half2(hy2, hy3));
    vl.x = h2_as_u32(__floats2half2_rn(x.x - __half2float(hx0), x.y - __half2float(hx1)));
    vl.y = h2_as_u32(__floats2half2_rn(x.z - __half2float(hx2), x.w - __half2float(hx3)));
    vl.z = h2_as_u32(__floats2half2_rn(y.x - __half2float(hy0), y.y - __half2float(hy1)));
    vl.w = h2_as_u32(__floats2half2_rn(y.z - __half2float(hy2), y.w - __half2float(hy3)));
    int off = st * 9216 + row * 144 + segpair * 16;
    *(uint4*)(sm + SA_HI + off) = vh;
    *(uint4*)(sm + SA_LO + off) = vl;
}

__global__ void __launch_bounds__(256, 2) k1_main(const float* __restrict__ ctx,
                                                  const float* __restrict__ V) {
    extern __shared__ char sm[];
    const int tid = threadIdx.x, lane = tid & 31, wid = tid >> 5;
    const int tile = blockIdx.x, h_half = blockIdx.y, b = blockIdx.z;
    const int cnt = g_cnt[b];
    if (tile * MS >= cnt) return;
    const int h_base = h_half * NH;

    float* sadd = (float*)(sm + SADD);
    float* sv   = (float*)(sm + SVV);
    float* satt = (float*)(sm + SATT);
    int*   sidx = (int*)(sm + SIDX);
    if (tid < NH) { sadd[tid] = g_add[b * H_ + h_base + tid]; sv[tid] = V[h_base + tid]; }
    if (tid < MS) {
        int ii = tile * MS + tid;
        if (ii >= cnt) ii = cnt - 1;
        sidx[tid] = g_idx[b * S_ + ii];
        satt[tid] = 0.0f;
    }
    __syncthreads();

    const uint32_t smb = smem_u32(sm);
    const int warp_s = wid & 1, warp_h = wid >> 1;

    // A gather: 64 rows x 8 seg-pairs = 512 pairs, 2 per thread
    const float* aptr[2];
    int arow[2], apair[2];
    #pragma unroll
    for (int it = 0; it < 2; it++) {
        int p = tid + it * 256;
        arow[it] = p >> 3; apair[it] = p & 7;
        aptr[it] = ctx + ((size_t)(b * S_ + sidx[arow[it]])) * D_ + apair[it] * 8;
    }
    // W cp.async: 256 rows x 8 segs(16B) = 2048, 8 per thread
    int wrow[8], wseg[8];
    #pragma unroll
    for (int it = 0; it < 8; it++) {
        int u = tid + it * 256;
        wrow[it] = u >> 3; wseg[it] = u & 7;
    }

    const uint32_t a_base = smb + SA_HI +
        (uint32_t)((warp_s * 32 + (lane & 15)) * 144 + (lane >> 4) * 16);
    const uint32_t b_base = smb + SW0 +
        (uint32_t)((warp_h * 64 + ((lane >> 4) & 1) * 8 + (lane & 7)) * 144 + ((lane >> 3) & 1) * 16);

    float acc[2][8][4];
    #pragma unroll
    for (int mt = 0; mt < 2; mt++)
        #pragma unroll
        for (int nt = 0; nt < 8; nt++)
            #pragma unroll
            for (int q = 0; q < 4; q++) acc[mt][nt][q] = 0.0f;

    // ---- prologue ----
    #pragma unroll
    for (int it = 0; it < 8; it++) {
        uint32_t dst = smb + SW0 + (uint32_t)(wrow[it] * 144 + wseg[it] * 16);
        size_t gb = (((size_t)(h_base + wrow[it])) << 10) + (wseg[it] << 4);
        CP_ASYNC16(dst, (const char*)g_Wh + gb);
    }
    CP_COMMIT();
    float4 apre[2][2];
    #pragma unroll
    for (int it = 0; it < 2; it++) {
        apre[it][0] = *(const float4*)(aptr[it]);
        apre[it][1] = *(const float4*)(aptr[it] + 4);
    }
    #pragma unroll
    for (int it = 0; it < 2; it++)
        store_a_pair(sm, 0, arow[it], apair[it], apre[it][0], apre[it][1]);
    #pragma unroll
    for (int it = 0; it < 2; it++) {
        apre[it][0] = *(const float4*)(aptr[it] + 64);
        apre[it][1] = *(const float4*)(aptr[it] + 68);
    }
    CP_WAIT0();
    __syncthreads();

    for (int kc = 0; kc < 8; kc++) {
        const int st = kc & 1;
        if (kc < 7) {
            const int st2 = st ^ 1;
            #pragma unroll
            for (int it = 0; it < 8; it++) {
                uint32_t dst = smb + SW0 + (uint32_t)(st2 * 36864 + wrow[it] * 144 + wseg[it] * 16);
                size_t gb = (((size_t)(h_base + wrow[it])) << 10) + (((size_t)(kc + 1)) << 7) + (wseg[it] << 4);
                CP_ASYNC16(dst, (const char*)g_Wh + gb);
            }
            CP_COMMIT();
            #pragma unroll
            for (int it = 0; it < 2; it++)
                store_a_pair(sm, st2, arow[it], apair[it], apre[it][0], apre[it][1]);
            if (kc < 6) {
                #pragma unroll
                for (int it = 0; it < 2; it++) {
                    apre[it][0] = *(const float4*)(aptr[it] + (kc + 2) * 64);
                    apre[it][1] = *(const float4*)(aptr[it] + (kc + 2) * 64 + 4);
                }
            }
        }
        // ---- MMAs on stage st: 2 terms (A hi + A lo) ----
        const uint32_t a_st = a_base + (uint32_t)(st * 9216);
        const uint32_t b_st = b_base + (uint32_t)(st * 36864);
        #pragma unroll
        for (int kk = 0; kk < 4; kk++) {
            uint32_t Ah[2][4], Al[2][4];
            #pragma unroll
            for (int mt = 0; mt < 2; mt++) {
                uint32_t ad = a_st + (uint32_t)(mt * 16 * 144 + kk * 32);
                LDSM4(Ah[mt][0], Ah[mt][1], Ah[mt][2], Ah[mt][3], ad);
                LDSM4(Al[mt][0], Al[mt][1], Al[mt][2], Al[mt][3], ad + 18432u);
            }
            #pragma unroll
            for (int nn = 0; nn < 4; nn++) {
                uint32_t bd = b_st + (uint32_t)(nn * 16 * 144 + kk * 32);
                uint32_t Bh[4];
                LDSM4(Bh[0], Bh[1], Bh[2], Bh[3], bd);
                #pragma unroll
                for (int mt = 0; mt < 2; mt++) {
                    MMAF16(acc[mt][2 * nn],     Ah[mt], Bh[0], Bh[1]);
                    MMAF16(acc[mt][2 * nn + 1], Ah[mt], Bh[2], Bh[3]);
                    MMAF16(acc[mt][2 * nn],     Al[mt], Bh[0], Bh[1]);
                    MMAF16(acc[mt][2 * nn + 1], Al[mt], Bh[2], Bh[3]);
                }
            }
        }
        if (kc < 7) { CP_WAIT0(); }
        __syncthreads();
    }

    // ---- epilogue ----
    float pa[4] = {0.f, 0.f, 0.f, 0.f};
    const int hb = warp_h * 64;
    #pragma unroll
    for (int nt = 0; nt < 8; nt++) {
        int h0 = hb + nt * 8 + 2 * (lane & 3);
        float v0 = sv[h0], v1 = sv[h0 + 1];
        float a0 = sadd[h0], a1 = sadd[h0 + 1];
        #pragma unroll
        for (int mt = 0; mt < 2; mt++) {
            #pragma unroll
            for (int rh = 0; rh < 2; rh++) {
                float x0 = acc[mt][nt][rh * 2 + 0] + a0;
                float x1 = acc[mt][nt][rh * 2 + 1] + a1;
                pa[mt * 2 + rh] = fmaf(v0, fast_tanh(x0), pa[mt * 2 + rh]);
                pa[mt * 2 + rh] = fmaf(v1, fast_tanh(x1), pa[mt * 2 + rh]);
            }
        }
    }
    #pragma unroll
    for (int q = 0; q < 4; q++) {
        pa[q] += __shfl_xor_sync(0xffffffffu, pa[q], 1);
        pa[q] += __shfl_xor_sync(0xffffffffu, pa[q], 2);
    }
    if ((lane & 3) == 0) {
        int r = lane >> 2;
        #pragma unroll
        for (int mt = 0; mt < 2; mt++)
            #pragma unroll
            for (int rh = 0; rh < 2; rh++)
                atomicAdd(&satt[warp_s * 32 + mt * 16 + rh * 8 + r], pa[mt * 2 + rh]);
    }
    __syncthreads();
    if (tid < MS) {
        int ii = tile * MS + tid;
        if (ii < cnt) atomicAdd(&g_att[b * S_ + ii], satt[tid]);
    }
}

// ---------------- K2: softmax ----------------
__device__ __forceinline__ float warp_max(float x) {
    #pragma unroll
    for (int o = 16; o; o >>= 1) x = fmaxf(x, __shfl_xor_sync(0xffffffffu, x, o));
    return x;
}
__device__ __forceinline__ float warp_sum(float x) {
    #pragma unroll
    for (int o = 16; o; o >>= 1) x += __shfl_xor_sync(0xffffffffu, x, o);
    return x;
}
__global__ void __launch_bounds__(1024) k2_softmax(float* __restrict__ out_alpha) {
    __shared__ float red[32];
    __shared__ float bc;
    int b = blockIdx.x, tid = threadIdx.x, lane = tid & 31, warp = tid >> 5;
    int cnt = g_cnt[b];
    const float NEG = -1e30f;
    float v[4];
    #pragma unroll
    for (int k = 0; k < 4; k++) {
        int i = tid + k * 1024;
        v[k] = (i < cnt) ? g_att[b * S_ + i] : NEG;
    }
    float m = fmaxf(fmaxf(v[0], v[1]), fmaxf(v[2], v[3]));
    m = warp_max(m);
    if (lane == 0) red[warp] = m;
    __syncthreads();
    if (warp == 0) { float t = warp_max(red[lane]); if (lane == 0) bc = t; }
    __syncthreads();
    m = bc;
    float s = 0.f;
    #pragma unroll
    for (int k = 0; k < 4; k++) s += __expf(v[k] - m);
    s = warp_sum(s);
    __syncthreads();
    if (lane == 0) red[warp] = s;
    __syncthreads();
    if (warp == 0) { float t = warp_sum(red[lane]); if (lane == 0) bc = t; }
    __syncthreads();
    float inv = 1.0f / bc;
    #pragma unroll
    for (int k = 0; k < 4; k++) out_alpha[b * S_ + tid + k * 1024] = 1e-6f;
    __syncthreads();
    #pragma unroll
    for (int k = 0; k < 4; k++) {
        int i = tid + k * 1024;
        if (i < cnt) {
            float al = __expf(v[k] - m) * inv;
            g_alpha[b * S_ + i] = al;
            out_alpha[b * S_ + g_idx[b * S_ + i]] = al + 1e-6f;
        }
    }
}

// ---------------- K3: cbar partials, float4 gather ----------------
__global__ void __launch_bounds__(128) k3_cbar(const float* __restrict__ ctx) {
    int sc = blockIdx.x, b = blockIdx.y;
    int tid = threadIdx.x;
    int d4 = tid * 4;
    __shared__ int   sIx[256];
    __shared__ float sAl[256];
    int cnt = g_cnt[b];
    int s0 = sc * 256, s1 = min(s0 + 256, cnt);
    int n = s1 - s0;
    if (n < 0) n = 0;
    for (int j = tid; j < 256; j += 128) {
        int i = s0 + j;
        sIx[j] = (i < s1) ? g_idx[b * S_ + i] : 0;
        sAl[j] = (i < s1) ? g_alpha[b * S_ + i] : 0.f;
    }
    __syncthreads();
    float4 a0 = {0,0,0,0}, a1 = {0,0,0,0}, a2 = {0,0,0,0}, a3 = {0,0,0,0};
    const size_t bS = (size_t)b * S_;
    int j = 0;
    for (; j + 3 < n; j += 4) {
        float4 c0 = *(const float4*)(ctx + (bS + sIx[j + 0]) * D_ + d4);
        float4 c1 = *(const float4*)(ctx + (bS + sIx[j + 1]) * D_ + d4);
        float4 c2 = *(const float4*)(ctx + (bS + sIx[j + 2]) * D_ + d4);
        float4 c3 = *(const float4*)(ctx + (bS + sIx[j + 3]) * D_ + d4);
        float w0 = sAl[j + 0], w1 = sAl[j + 1], w2 = sAl[j + 2], w3 = sAl[j + 3];
        a0.x = fmaf(w0, c0.x, a0.x); a0.y = fmaf(w0, c0.y, a0.y);
        a0.z = fmaf(w0, c0.z, a0.z); a0.w = fmaf(w0, c0.w, a0.w);
        a1.x = fmaf(w1, c1.x, a1.x); a1.y = fmaf(w1, c1.y, a1.y);
        a1.z = fmaf(w1, c1.z, a1.z); a1.w = fmaf(w1, c1.w, a1.w);
        a2.x = fmaf(w2, c2.x, a2.x); a2.y = fmaf(w2, c2.y, a2.y);
        a2.z = fmaf(w2, c2.z, a2.z); a2.w = fmaf(w2, c2.w, a2.w);
        a3.x = fmaf(w3, c3.x, a3.x); a3.y = fmaf(w3, c3.y, a3.y);
        a3.z = fmaf(w3, c3.z, a3.z); a3.w = fmaf(w3, c3.w, a3.w);
    }
    for (; j < n; j++) {
        float4 c = *(const float4*)(ctx + (bS + sIx[j]) * D_ + d4);
        float w = sAl[j];
        a0.x = fmaf(w, c.x, a0.x); a0.y = fmaf(w, c.y, a0.y);
        a0.z = fmaf(w, c.z, a0.z); a0.w = fmaf(w, c.w, a0.w);
    }
    float4 r;
    r.x = (a0.x + a1.x) + (a2.x + a3.x);
    r.y = (a0.y + a1.y) + (a2.y + a3.y);
    r.z = (a0.z + a1.z) + (a2.z + a3.z);
    r.w = (a0.w + a1.w) + (a2.w + a3.w);
    *(float4*)(g_cbar_part + ((size_t)b * 16 + sc) * D_ + d4) = r;
}

// ---------------- K3b ----------------
__global__ void __launch_bounds__(512) k3b_reduce() {
    int b = blockIdx.x, d = threadIdx.x;
    float acc = 0.f;
    #pragma unroll
    for (int p = 0; p < 16; p++) acc += g_cbar_part[((size_t)b * 16 + p) * D_ + d];
    g_cbar[b * D_ + d] = acc;
}

// ---------------- K4 ----------------
__global__ void __launch_bounds__(256) k4_hidden(const float* __restrict__ W_ctx,
                                                 const float* __restrict__ b_ctx,
                                                 float* __restrict__ out) {
    int gw = blockIdx.x * 8 + (threadIdx.x >> 5);
    int lane = threadIdx.x & 31;
    int b = gw >> 9, h = gw & 511;
    const float* w = W_ctx + (size_t)h * D_;
    const float* cb = g_cbar + (size_t)b * D_;
    float s = 0.f;
    #pragma unroll
    for (int i = 0; i < 16; i++) {
        int d = lane + 32 * i;
        s = fmaf(w[d], cb[d], s);
    }
    #pragma unroll
    for (int o = 16; o; o >>= 1) s += __shfl_xor_sync(0xffffffffu, s, o);
    if (lane == 0) out[b * H_ + h] = s + b_ctx[h];
}

// ---------------- launch ----------------
extern "C" void kernel_launch(void* const* d_in, const int* in_sizes, int n_in,
                              void* d_out, int out_size) {
    const float* input   = (const float*)d_in[0];
    const float* context = (const float*)d_in[1];
    const int*   mask    = (const int*)d_in[2];
    const float* W_in  = (const float*)d_in[3];
    const float* b_in  = (const float*)d_in[4];
    const float* W_ctx = (const float*)d_in[5];
    const float* b_ctx = (const float*)d_in[6];
    const float* V     = (const float*)d_in[7];
    float* out = (float*)d_out;

    cudaFuncSetAttribute(k1_main, cudaFuncAttributeMaxDynamicSharedMemorySize, SMEM_K1);

    k0a_split<<<(H_ * D_ + 255) / 256, 256>>>(W_ctx);
    k0b_add<<<B_ * H_ / 8, 256>>>(input, W_in, b_in, b_ctx);
    k0c_compact<<<B_, 256>>>(mask);
    k1_main<<<dim3(S_ / MS, 2, B_), 256, SMEM_K1>>>(context, V);
    k2_softmax<<<B_, 1024>>>(out + B_ * H_);
    k3_cbar<<<dim3(16, B_), 128>>>(context);
    k3b_reduce<<<B_, 512>>>();
    k4_hidden<<<B_ * H_ / 8, 256>>>(W_ctx, b_ctx, out);
}

// round 11
// speedup vs baseline: 1.3164x; 1.3164x over previous
#include <cuda_runtime.h>
#include <cuda_fp16.h>
#include <cstdint>

#define B_ 32
#define S_ 4096
#define D_ 512
#define H_ 512

// ---------------- device scratch ----------------
__device__ float  g_add[B_ * H_];
__device__ __half g_Wh[H_ * D_];
__device__ float  g_att[B_ * S_];
__device__ float  g_alpha[B_ * S_];
__device__ float  g_cbar_part[B_ * 16 * D_];
__device__ float  g_cbar[B_ * D_];
__device__ int    g_idx[B_ * S_];
__device__ int    g_cnt[B_];

// ---------------- helpers ----------------
__device__ __forceinline__ uint32_t smem_u32(const void* p) {
    uint32_t a;
    asm("{ .reg .u64 t; cvta.to.shared.u64 t, %1; cvt.u32.u64 %0, t; }" : "=r"(a) : "l"(p));
    return a;
}

__device__ __forceinline__ uint32_t h2_as_u32(__half2 h) {
    union { __half2 h; uint32_t u; } cvt;
    cvt.h = h;
    return cvt.u;
}

#define LDSM4(r0, r1, r2, r3, addr) \
    asm volatile("ldmatrix.sync.aligned.m8n8.x4.shared.b16 {%0,%1,%2,%3}, [%4];" \
                 : "=r"(r0), "=r"(r1), "=r"(r2), "=r"(r3) : "r"(addr))

#define MMAF16(d, a, b0, b1) \
    asm volatile("mma.sync.aligned.m16n8k16.row.col.f32.f16.f16.f32 " \
                 "{%0,%1,%2,%3}, {%4,%5,%6,%7}, {%8,%9}, {%0,%1,%2,%3};" \
                 : "+f"((d)[0]), "+f"((d)[1]), "+f"((d)[2]), "+f"((d)[3]) \
                 : "r"((a)[0]), "r"((a)[1]), "r"((a)[2]), "r"((a)[3]), "r"(b0), "r"(b1))

#define CP_ASYNC16(dst, src) \
    asm volatile("cp.async.cg.shared.global [%0], [%1], 16;" :: "r"(dst), "l"(src))
#define CP_COMMIT()  asm volatile("cp.async.commit_group;")
#define CP_WAITG(n)  asm volatile("cp.async.wait_group %0;" :: "n"(n))

// Accurate tanh with NO MUFU. abs err ~1e-5.
__device__ __forceinline__ float fast_tanh(float x) {
    float ax = fabsf(x);
    float z  = fminf(ax * 2.8853900817779268f, 30.0f);
    float zf = z + 12582912.0f;
    int   ni = __float_as_int(zf) - 0x4B400000;
    float fr = z - (zf - 12582912.0f);
    float p  = 1.3333558146e-3f;
    p = fmaf(p, fr, 9.6181291076e-3f);
    p = fmaf(p, fr, 5.5504108665e-2f);
    p = fmaf(p, fr, 2.4022650696e-1f);
    p = fmaf(p, fr, 6.9314718056e-1f);
    p = fmaf(p, fr, 1.0f);
    float u = __int_as_float((ni + 127) << 23) * p;
    float d = u + 1.0f;
    float r = __int_as_float(0x7EF311C3u - __float_as_uint(d));
    r = r * fmaf(-d, r, 2.0f);
    r = r * fmaf(-d, r, 2.0f);
    float t = fmaf(-2.0f, r, 1.0f);
    return copysignf(t, x);
}

// ---------------- K0a: W_ctx -> fp16 ----------------
__global__ void k0a_split(const float* __restrict__ W) {
    int i = blockIdx.x * 256 + threadIdx.x;
    if (i < H_ * D_) g_Wh[i] = __float2half_rn(W[i]);
}

// ---------------- K0b ----------------
__global__ void __launch_bounds__(256) k0b_add(const float* __restrict__ input,
                                               const float* __restrict__ W_in,
                                               const float* __restrict__ b_in,
                                               const float* __restrict__ b_ctx) {
    int gw = blockIdx.x * 8 + (threadIdx.x >> 5);
    int lane = threadIdx.x & 31;
    int b = gw >> 9, h = gw & 511;
    const float* w = W_in + (size_t)h * D_;
    const float* in = input + (size_t)b * D_;
    float s = 0.f;
    #pragma unroll
    for (int i = 0; i < 16; i++) {
        int d = lane + 32 * i;
        s = fmaf(w[d], in[d], s);
    }
    #pragma unroll
    for (int o = 16; o; o >>= 1) s += __shfl_xor_sync(0xffffffffu, s, o);
    if (lane == 0) g_add[b * H_ + h] = s + b_in[h] + b_ctx[h];
}

// ---------------- K0c ----------------
__global__ void __launch_bounds__(256) k0c_compact(const int* __restrict__ mask) {
    int b = blockIdx.x, tid = threadIdx.x, lane = tid & 31;
    for (int i = tid; i < S_; i += 256) g_att[b * S_ + i] = 0.f;
    if (tid < 32) {
        int base = 0;
        for (int s0 = 0; s0 < S_; s0 += 32) {
            int s = s0 + lane;
            bool keep = (mask[b * S_ + s] == 0);
            unsigned bal = __ballot_sync(0xffffffffu, keep);
            int rank = __popc(bal & ((1u << lane) - 1u));
            if (keep) g_idx[b * S_ + base + rank] = s;
            base += __popc(bal);
        }
        if (lane == 0) g_cnt[b] = base;
    }
}

// ---------------- K1: fp16 single-term GEMM, 4-stage depth-2 pipeline ----------------
// 512 threads, 16 warps (4s x 4h), warp tile 32x64. CTA tile M=128, N=256, K=512 (8 x 64).
#define MS 128
#define NH 256
#define ASTG 18432          // A stage: 128 rows * 144B
#define WSTG 36864          // W stage: 256 rows * 144B
#define SW0  73728          // A stages [0, 73728), W stages [73728, 221184)
#define SADD 221184
#define SVV  222208
#define SATT 223232
#define SIDX 223744
#define SMEM_K1 224256

// store 8 consecutive fp32 as 8 fp16 = 16B
__device__ __forceinline__ void store_a_pair(char* sm, int st, int row, int segpair,
                                             float4 x, float4 y) {
    uint4 v;
    v.x = h2_as_u32(__floats2half2_rn(x.x, x.y));
    v.y = h2_as_u32(__floats2half2_rn(x.z, x.w));
    v.z = h2_as_u32(__floats2half2_rn(y.x, y.y));
    v.w = h2_as_u32(__floats2half2_rn(y.z, y.w));
    *(uint4*)(sm + st * ASTG + row * 144 + segpair * 16) = v;
}

__global__ void __launch_bounds__(512, 1) k1_main(const float* __restrict__ ctx,
                                                  const float* __restrict__ V) {
    extern __shared__ char sm[];
    const int tid = threadIdx.x, lane = tid & 31, wid = tid >> 5;
    const int tile = blockIdx.x, h_half = blockIdx.y, b = blockIdx.z;
    const int cnt = g_cnt[b];
    if (tile * MS >= cnt) return;
    const int h_base = h_half * NH;

    float* sadd = (float*)(sm + SADD);
    float* sv   = (float*)(sm + SVV);
    float* satt = (float*)(sm + SATT);
    int*   sidx = (int*)(sm + SIDX);
    if (tid < NH) { sadd[tid] = g_add[b * H_ + h_base + tid]; sv[tid] = V[h_base + tid]; }
    if (tid < MS) {
        int ii = tile * MS + tid;
        if (ii >= cnt) ii = cnt - 1;
        sidx[tid] = g_idx[b * S_ + ii];
        satt[tid] = 0.0f;
    }
    __syncthreads();

    const uint32_t smb = smem_u32(sm);
    const int warp_s = wid & 3, warp_h = wid >> 2;

    // A gather: 128 rows x 8 seg-pairs (16B fp16 each) = 1024 pairs, 2 per thread
    const float* aptr[2];
    int arow[2], apair[2];
    #pragma unroll
    for (int it = 0; it < 2; it++) {
        int p = tid + it * 512;
        arow[it] = p >> 3; apair[it] = p & 7;
        aptr[it] = ctx + ((size_t)(b * S_ + sidx[arow[it]])) * D_ + apair[it] * 8;
    }
    // W cp.async: 256 rows x 8 segs(16B) = 2048, 4 per thread
    int wrow[4], wseg[4];
    #pragma unroll
    for (int it = 0; it < 4; it++) {
        int u = tid + it * 512;
        wrow[it] = u >> 3; wseg[it] = u & 7;
    }

    const uint32_t a_base = smb + (uint32_t)((warp_s * 32 + (lane & 15)) * 144 + (lane >> 4) * 16);
    const uint32_t b_base = smb + SW0 +
        (uint32_t)((warp_h * 64 + ((lane >> 4) & 1) * 8 + (lane & 7)) * 144 + ((lane >> 3) & 1) * 16);

    float acc[2][8][4];
    #pragma unroll
    for (int mt = 0; mt < 2; mt++)
        #pragma unroll
        for (int nt = 0; nt < 8; nt++)
            #pragma unroll
            for (int q = 0; q < 4; q++) acc[mt][nt][q] = 0.0f;

    // ---- prologue: W(0), W(1) cp.async (two groups); A(0) -> st0; A(1) -> regs ----
    #pragma unroll
    for (int it = 0; it < 4; it++) {
        uint32_t dst = smb + SW0 + (uint32_t)(wrow[it] * 144 + wseg[it] * 16);
        size_t gb = (((size_t)(h_base + wrow[it])) << 10) + (wseg[it] << 4);
        CP_ASYNC16(dst, (const char*)g_Wh + gb);
    }
    CP_COMMIT();
    #pragma unroll
    for (int it = 0; it < 4; it++) {
        uint32_t dst = smb + SW0 + (uint32_t)(WSTG + wrow[it] * 144 + wseg[it] * 16);
        size_t gb = (((size_t)(h_base + wrow[it])) << 10) + (1u << 7) + (wseg[it] << 4);
        CP_ASYNC16(dst, (const char*)g_Wh + gb);
    }
    CP_COMMIT();
    float4 apre[2][2];
    #pragma unroll
    for (int it = 0; it < 2; it++) {
        apre[it][0] = *(const float4*)(aptr[it]);
        apre[it][1] = *(const float4*)(aptr[it] + 4);
    }
    #pragma unroll
    for (int it = 0; it < 2; it++)
        store_a_pair(sm, 0, arow[it], apair[it], apre[it][0], apre[it][1]);
    #pragma unroll
    for (int it = 0; it < 2; it++) {
        apre[it][0] = *(const float4*)(aptr[it] + 64);
        apre[it][1] = *(const float4*)(aptr[it] + 68);
    }

    #pragma unroll
    for (int kc = 0; kc < 8; kc++) {
        const int st = kc & 3;
        // ---- producers (into stages not read until >= 2 barriers from now) ----
        if (kc < 7) {
            #pragma unroll
            for (int it = 0; it < 2; it++)
                store_a_pair(sm, (kc + 1) & 3, arow[it], apair[it], apre[it][0], apre[it][1]);
        }
        if (kc < 6) {
            const int st2 = (kc + 2) & 3;
            #pragma unroll
            for (int it = 0; it < 4; it++) {
                uint32_t dst = smb + SW0 + (uint32_t)(st2 * WSTG + wrow[it] * 144 + wseg[it] * 16);
                size_t gb = (((size_t)(h_base + wrow[it])) << 10) + (((size_t)(kc + 2)) << 7) + (wseg[it] << 4);
                CP_ASYNC16(dst, (const char*)g_Wh + gb);
            }
            CP_COMMIT();
            #pragma unroll
            for (int it = 0; it < 2; it++) {
                apre[it][0] = *(const float4*)(aptr[it] + (kc + 2) * 64);
                apre[it][1] = *(const float4*)(aptr[it] + (kc + 2) * 64 + 4);
            }
        }
        // ---- ensure W(kc) group landed (depth-2: groups kc+1, kc+2 stay in flight) ----
        if (kc < 6)      { CP_WAITG(2); }
        else if (kc == 6){ CP_WAITG(1); }
        else             { CP_WAITG(0); }
        __syncthreads();
        // ---- MMAs on stage st ----
        const uint32_t a_st = a_base + (uint32_t)(st * ASTG);
        const uint32_t b_st = b_base + (uint32_t)(st * WSTG);
        #pragma unroll
        for (int kk = 0; kk < 4; kk++) {
            uint32_t A[2][4];
            #pragma unroll
            for (int mt = 0; mt < 2; mt++) {
                uint32_t ad = a_st + (uint32_t)(mt * 16 * 144 + kk * 32);
                LDSM4(A[mt][0], A[mt][1], A[mt][2], A[mt][3], ad);
            }
            #pragma unroll
            for (int nn = 0; nn < 4; nn++) {
                uint32_t bd = b_st + (uint32_t)(nn * 16 * 144 + kk * 32);
                uint32_t Bh[4];
                LDSM4(Bh[0], Bh[1], Bh[2], Bh[3], bd);
                #pragma unroll
                for (int mt = 0; mt < 2; mt++) {
                    MMAF16(acc[mt][2 * nn],     A[mt], Bh[0], Bh[1]);
                    MMAF16(acc[mt][2 * nn + 1], A[mt], Bh[2], Bh[3]);
                }
            }
        }
    }

    // ---- epilogue ----
    float pa[4] = {0.f, 0.f, 0.f, 0.f};
    const int hb = warp_h * 64;
    #pragma unroll
    for (int nt = 0; nt < 8; nt++) {
        int h0 = hb + nt * 8 + 2 * (lane & 3);
        float v0 = sv[h0], v1 = sv[h0 + 1];
        float a0 = sadd[h0], a1 = sadd[h0 + 1];
        #pragma unroll
        for (int mt = 0; mt < 2; mt++) {
            #pragma unroll
            for (int rh = 0; rh < 2; rh++) {
                float x0 = acc[mt][nt][rh * 2 + 0] + a0;
                float x1 = acc[mt][nt][rh * 2 + 1] + a1;
                pa[mt * 2 + rh] = fmaf(v0, fast_tanh(x0), pa[mt * 2 + rh]);
                pa[mt * 2 + rh] = fmaf(v1, fast_tanh(x1), pa[mt * 2 + rh]);
            }
        }
    }
    #pragma unroll
    for (int q = 0; q < 4; q++) {
        pa[q] += __shfl_xor_sync(0xffffffffu, pa[q], 1);
        pa[q] += __shfl_xor_sync(0xffffffffu, pa[q], 2);
    }
    __syncthreads();   // satt was zeroed before; MMA loop done for all warps
    if ((lane & 3) == 0) {
        int r = lane >> 2;
        #pragma unroll
        for (int mt = 0; mt < 2; mt++)
            #pragma unroll
            for (int rh = 0; rh < 2; rh++)
                atomicAdd(&satt[warp_s * 32 + mt * 16 + rh * 8 + r], pa[mt * 2 + rh]);
    }
    __syncthreads();
    if (tid < MS) {
        int ii = tile * MS + tid;
        if (ii < cnt) atomicAdd(&g_att[b * S_ + ii], satt[tid]);
    }
}

// ---------------- K2: softmax ----------------
__device__ __forceinline__ float warp_max(float x) {
    #pragma unroll
    for (int o = 16; o; o >>= 1) x = fmaxf(x, __shfl_xor_sync(0xffffffffu, x, o));
    return x;
}
__device__ __forceinline__ float warp_sum(float x) {
    #pragma unroll
    for (int o = 16; o; o >>= 1) x += __shfl_xor_sync(0xffffffffu, x, o);
    return x;
}
__global__ void __launch_bounds__(1024) k2_softmax(float* __restrict__ out_alpha) {
    __shared__ float red[32];
    __shared__ float bc;
    int b = blockIdx.x, tid = threadIdx.x, lane = tid & 31, warp = tid >> 5;
    int cnt = g_cnt[b];
    const float NEG = -1e30f;
    float v[4];
    #pragma unroll
    for (int k = 0; k < 4; k++) {
        int i = tid + k * 1024;
        v[k] = (i < cnt) ? g_att[b * S_ + i] : NEG;
    }
    float m = fmaxf(fmaxf(v[0], v[1]), fmaxf(v[2], v[3]));
    m = warp_max(m);
    if (lane == 0) red[warp] = m;
    __syncthreads();
    if (warp == 0) { float t = warp_max(red[lane]); if (lane == 0) bc = t; }
    __syncthreads();
    m = bc;
    float s = 0.f;
    #pragma unroll
    for (int k = 0; k < 4; k++) s += __expf(v[k] - m);
    s = warp_sum(s);
    __syncthreads();
    if (lane == 0) red[warp] = s;
    __syncthreads();
    if (warp == 0) { float t = warp_sum(red[lane]); if (lane == 0) bc = t; }
    __syncthreads();
    float inv = 1.0f / bc;
    #pragma unroll
    for (int k = 0; k < 4; k++) out_alpha[b * S_ + tid + k * 1024] = 1e-6f;
    __syncthreads();
    #pragma unroll
    for (int k = 0; k < 4; k++) {
        int i = tid + k * 1024;
        if (i < cnt) {
            float al = __expf(v[k] - m) * inv;
            g_alpha[b * S_ + i] = al;
            out_alpha[b * S_ + g_idx[b * S_ + i]] = al + 1e-6f;
        }
    }
}

// ---------------- K3: cbar partials, float4 gather ----------------
__global__ void __launch_bounds__(128) k3_cbar(const float* __restrict__ ctx) {
    int sc = blockIdx.x, b = blockIdx.y;
    int tid = threadIdx.x;
    int d4 = tid * 4;
    __shared__ int   sIx[256];
    __shared__ float sAl[256];
    int cnt = g_cnt[b];
    int s0 = sc * 256, s1 = min(s0 + 256, cnt);
    int n = s1 - s0;
    if (n < 0) n = 0;
    for (int j = tid; j < 256; j += 128) {
        int i = s0 + j;
        sIx[j] = (i < s1) ? g_idx[b * S_ + i] : 0;
        sAl[j] = (i < s1) ? g_alpha[b * S_ + i] : 0.f;
    }
    __syncthreads();
    float4 a0 = {0,0,0,0}, a1 = {0,0,0,0}, a2 = {0,0,0,0}, a3 = {0,0,0,0};
    const size_t bS = (size_t)b * S_;
    int j = 0;
    for (; j + 3 < n; j += 4) {
        float4 c0 = *(const float4*)(ctx + (bS + sIx[j + 0]) * D_ + d4);
        float4 c1 = *(const float4*)(ctx + (bS + sIx[j + 1]) * D_ + d4);
        float4 c2 = *(const float4*)(ctx + (bS + sIx[j + 2]) * D_ + d4);
        float4 c3 = *(const float4*)(ctx + (bS + sIx[j + 3]) * D_ + d4);
        float w0 = sAl[j + 0], w1 = sAl[j + 1], w2 = sAl[j + 2], w3 = sAl[j + 3];
        a0.x = fmaf(w0, c0.x, a0.x); a0.y = fmaf(w0, c0.y, a0.y);
        a0.z = fmaf(w0, c0.z, a0.z); a0.w = fmaf(w0, c0.w, a0.w);
        a1.x = fmaf(w1, c1.x, a1.x); a1.y = fmaf(w1, c1.y, a1.y);
        a1.z = fmaf(w1, c1.z, a1.z); a1.w = fmaf(w1, c1.w, a1.w);
        a2.x = fmaf(w2, c2.x, a2.x); a2.y = fmaf(w2, c2.y, a2.y);
        a2.z = fmaf(w2, c2.z, a2.z); a2.w = fmaf(w2, c2.w, a2.w);
        a3.x = fmaf(w3, c3.x, a3.x); a3.y = fmaf(w3, c3.y, a3.y);
        a3.z = fmaf(w3, c3.z, a3.z); a3.w = fmaf(w3, c3.w, a3.w);
    }
    for (; j < n; j++) {
        float4 c = *(const float4*)(ctx + (bS + sIx[j]) * D_ + d4);
        float w = sAl[j];
        a0.x = fmaf(w, c.x, a0.x); a0.y = fmaf(w, c.y, a0.y);
        a0.z = fmaf(w, c.z, a0.z); a0.w = fmaf(w, c.w, a0.w);
    }
    float4 r;
    r.x = (a0.x + a1.x) + (a2.x + a3.x);
    r.y = (a0.y + a1.y) + (a2.y + a3.y);
    r.z = (a0.z + a1.z) + (a2.z + a3.z);
    r.w = (a0.w + a1.w) + (a2.w + a3.w);
    *(float4*)(g_cbar_part + ((size_t)b * 16 + sc) * D_ + d4) = r;
}

// ---------------- K3b ----------------
__global__ void __launch_bounds__(512) k3b_reduce() {
    int b = blockIdx.x, d = threadIdx.x;
    float acc = 0.f;
    #pragma unroll
    for (int p = 0; p < 16; p++) acc += g_cbar_part[((size_t)b * 16 + p) * D_ + d];
    g_cbar[b * D_ + d] = acc;
}

// ---------------- K4 ----------------
__global__ void __launch_bounds__(256) k4_hidden(const float* __restrict__ W_ctx,
                                                 const float* __restrict__ b_ctx,
                                                 float* __restrict__ out) {
    int gw = blockIdx.x * 8 + (threadIdx.x >> 5);
    int lane = threadIdx.x & 31;
    int b = gw >> 9, h = gw & 511;
    const float* w = W_ctx + (size_t)h * D_;
    const float* cb = g_cbar + (size_t)b * D_;
    float s = 0.f;
    #pragma unroll
    for (int i = 0; i < 16; i++) {
        int d = lane + 32 * i;
        s = fmaf(w[d], cb[d], s);
    }
    #pragma unroll
    for (int o = 16; o; o >>= 1) s += __shfl_xor_sync(0xffffffffu, s, o);
    if (lane == 0) out[b * H_ + h] = s + b_ctx[h];
}

// ---------------- launch ----------------
extern "C" void kernel_launch(void* const* d_in, const int* in_sizes, int n_in,
                              void* d_out, int out_size) {
    const float* input   = (const float*)d_in[0];
    const float* context = (const float*)d_in[1];
    const int*   mask    = (const int*)d_in[2];
    const float* W_in  = (const float*)d_in[3];
    const float* b_in  = (const float*)d_in[4];
    const float* W_ctx = (const float*)d_in[5];
    const float* b_ctx = (const float*)d_in[6];
    const float* V     = (const float*)d_in[7];
    float* out = (float*)d_out;

    cudaFuncSetAttribute(k1_main, cudaFuncAttributeMaxDynamicSharedMemorySize, SMEM_K1);

    k0a_split<<<(H_ * D_ + 255) / 256, 256>>>(W_ctx);
    k0b_add<<<B_ * H_ / 8, 256>>>(input, W_in, b_in, b_ctx);
    k0c_compact<<<B_, 256>>>(mask);
    k1_main<<<dim3(S_ / MS, 2, B_), 512, SMEM_K1>>>(context, V);
    k2_softmax<<<B_, 1024>>>(out + B_ * H_);
    k3_cbar<<<dim3(16, B_), 128>>>(context);
    k3b_reduce<<<B_, 512>>>();
    k4_hidden<<<B_ * H_ / 8, 256>>>(W_ctx, b_ctx, out);
}

// round 12
// speedup vs baseline: 1.3422x; 1.0196x over previous
#include <cuda_runtime.h>
#include <cuda_fp16.h>
#include <cstdint>

#define B_ 32
#define S_ 4096
#define D_ 512
#define H_ 512

// ---------------- device scratch ----------------
__device__ float  g_add[B_ * H_];
__device__ __half g_Wh[H_ * D_];
__device__ float  g_att[B_ * S_];
__device__ float  g_alpha[B_ * S_];
__device__ float  g_cbar_part[B_ * 16 * D_];
__device__ float  g_cbar[B_ * D_];
__device__ int    g_idx[B_ * S_];
__device__ int    g_cnt[B_];

// ---------------- helpers ----------------
__device__ __forceinline__ uint32_t smem_u32(const void* p) {
    uint32_t a;
    asm("{ .reg .u64 t; cvta.to.shared.u64 t, %1; cvt.u32.u64 %0, t; }" : "=r"(a) : "l"(p));
    return a;
}

__device__ __forceinline__ uint32_t h2_as_u32(__half2 h) {
    union { __half2 h; uint32_t u; } cvt;
    cvt.h = h;
    return cvt.u;
}

#define LDSM4(r0, r1, r2, r3, addr) \
    asm volatile("ldmatrix.sync.aligned.m8n8.x4.shared.b16 {%0,%1,%2,%3}, [%4];" \
                 : "=r"(r0), "=r"(r1), "=r"(r2), "=r"(r3) : "r"(addr))

#define MMAF16(d, a, b0, b1) \
    asm volatile("mma.sync.aligned.m16n8k16.row.col.f32.f16.f16.f32 " \
                 "{%0,%1,%2,%3}, {%4,%5,%6,%7}, {%8,%9}, {%0,%1,%2,%3};" \
                 : "+f"((d)[0]), "+f"((d)[1]), "+f"((d)[2]), "+f"((d)[3]) \
                 : "r"((a)[0]), "r"((a)[1]), "r"((a)[2]), "r"((a)[3]), "r"(b0), "r"(b1))

#define CP_ASYNC16(dst, src) \
    asm volatile("cp.async.cg.shared.global [%0], [%1], 16;" :: "r"(dst), "l"(src))
#define CP_COMMIT()  asm volatile("cp.async.commit_group;")
#define CP_WAITG(n)  asm volatile("cp.async.wait_group %0;" :: "n"(n))

// Accurate tanh with NO MUFU. abs err ~1e-5.
__device__ __forceinline__ float fast_tanh(float x) {
    float ax = fabsf(x);
    float z  = fminf(ax * 2.8853900817779268f, 30.0f);
    float zf = z + 12582912.0f;
    int   ni = __float_as_int(zf) - 0x4B400000;
    float fr = z - (zf - 12582912.0f);
    float p  = 1.3333558146e-3f;
    p = fmaf(p, fr, 9.6181291076e-3f);
    p = fmaf(p, fr, 5.5504108665e-2f);
    p = fmaf(p, fr, 2.4022650696e-1f);
    p = fmaf(p, fr, 6.9314718056e-1f);
    p = fmaf(p, fr, 1.0f);
    float u = __int_as_float((ni + 127) << 23) * p;
    float d = u + 1.0f;
    float r = __int_as_float(0x7EF311C3u - __float_as_uint(d));
    r = r * fmaf(-d, r, 2.0f);
    r = r * fmaf(-d, r, 2.0f);
    float t = fmaf(-2.0f, r, 1.0f);
    return copysignf(t, x);
}

// ---------------- K0 fused: W->fp16 | add | compact (independent jobs) ----------------
__global__ void __launch_bounds__(256) k0_fused(const float* __restrict__ W_ctx,
                                                const float* __restrict__ input,
                                                const float* __restrict__ W_in,
                                                const float* __restrict__ b_in,
                                                const float* __restrict__ b_ctx,
                                                const int* __restrict__ mask) {
    int bx = blockIdx.x, tid = threadIdx.x;
    if (bx < 1024) {
        // job A: W_ctx -> fp16 (262144 elems)
        int i = bx * 256 + tid;
        g_Wh[i] = __float2half_rn(W_ctx[i]);
    } else if (bx < 3072) {
        // job B: add[b,h] = input@W_in^T + b_in + b_ctx (warp-per-dot)
        int gw = (bx - 1024) * 8 + (tid >> 5);
        int lane = tid & 31;
        int b = gw >> 9, h = gw & 511;
        const float* w = W_in + (size_t)h * D_;
        const float* in = input + (size_t)b * D_;
        float s = 0.f;
        #pragma unroll
        for (int i = 0; i < 16; i++) {
            int d = lane + 32 * i;
            s = fmaf(w[d], in[d], s);
        }
        #pragma unroll
        for (int o = 16; o; o >>= 1) s += __shfl_xor_sync(0xffffffffu, s, o);
        if (lane == 0) g_add[b * H_ + h] = s + b_in[h] + b_ctx[h];
    } else {
        // job C: compact unmasked indices + zero g_att
        int b = bx - 3072, lane = tid & 31;
        for (int i = tid; i < S_; i += 256) g_att[b * S_ + i] = 0.f;
        if (tid < 32) {
            int base = 0;
            for (int s0 = 0; s0 < S_; s0 += 32) {
                int s = s0 + lane;
                bool keep = (mask[b * S_ + s] == 0);
                unsigned bal = __ballot_sync(0xffffffffu, keep);
                int rank = __popc(bal & ((1u << lane) - 1u));
                if (keep) g_idx[b * S_ + base + rank] = s;
                base += __popc(bal);
            }
            if (lane == 0) g_cnt[b] = base;
        }
    }
}

// ---------------- K1: fp16 single-term GEMM, 4-stage depth-2 pipeline, hoisted LDSM ----------------
// 512 threads, 16 warps (4s x 4h), warp tile 32x64. CTA tile M=128, N=256, K=512 (8 x 64).
#define MS 128
#define NH 256
#define ASTG 18432          // A stage: 128 rows * 144B
#define WSTG 36864          // W stage: 256 rows * 144B
#define SW0  73728          // A stages [0, 73728), W stages [73728, 221184)
#define SADD 221184
#define SVV  222208
#define SATT 223232
#define SIDX 223744
#define SMEM_K1 224256

// store 8 consecutive fp32 as 8 fp16 = 16B
__device__ __forceinline__ void store_a_pair(char* sm, int st, int row, int segpair,
                                             float4 x, float4 y) {
    uint4 v;
    v.x = h2_as_u32(__floats2half2_rn(x.x, x.y));
    v.y = h2_as_u32(__floats2half2_rn(x.z, x.w));
    v.z = h2_as_u32(__floats2half2_rn(y.x, y.y));
    v.w = h2_as_u32(__floats2half2_rn(y.z, y.w));
    *(uint4*)(sm + st * ASTG + row * 144 + segpair * 16) = v;
}

__global__ void __launch_bounds__(512, 1) k1_main(const float* __restrict__ ctx,
                                                  const float* __restrict__ V) {
    extern __shared__ char sm[];
    const int tid = threadIdx.x, lane = tid & 31, wid = tid >> 5;
    const int tile = blockIdx.x, h_half = blockIdx.y, b = blockIdx.z;
    const int cnt = g_cnt[b];
    if (tile * MS >= cnt) return;
    const int h_base = h_half * NH;

    float* sadd = (float*)(sm + SADD);
    float* sv   = (float*)(sm + SVV);
    float* satt = (float*)(sm + SATT);
    int*   sidx = (int*)(sm + SIDX);
    if (tid < NH) { sadd[tid] = g_add[b * H_ + h_base + tid]; sv[tid] = V[h_base + tid]; }
    if (tid < MS) {
        int ii = tile * MS + tid;
        if (ii >= cnt) ii = cnt - 1;
        sidx[tid] = g_idx[b * S_ + ii];
        satt[tid] = 0.0f;
    }
    __syncthreads();

    const uint32_t smb = smem_u32(sm);
    const int warp_s = wid & 3, warp_h = wid >> 2;

    // A gather: 128 rows x 8 seg-pairs (16B fp16 each) = 1024 pairs, 2 per thread
    const float* aptr[2];
    int arow[2], apair[2];
    #pragma unroll
    for (int it = 0; it < 2; it++) {
        int p = tid + it * 512;
        arow[it] = p >> 3; apair[it] = p & 7;
        aptr[it] = ctx + ((size_t)(b * S_ + sidx[arow[it]])) * D_ + apair[it] * 8;
    }
    // W cp.async: 256 rows x 8 segs(16B) = 2048, 4 per thread
    int wrow[4], wseg[4];
    #pragma unroll
    for (int it = 0; it < 4; it++) {
        int u = tid + it * 512;
        wrow[it] = u >> 3; wseg[it] = u & 7;
    }

    const uint32_t a_base = smb + (uint32_t)((warp_s * 32 + (lane & 15)) * 144 + (lane >> 4) * 16);
    const uint32_t b_base = smb + SW0 +
        (uint32_t)((warp_h * 64 + ((lane >> 4) & 1) * 8 + (lane & 7)) * 144 + ((lane >> 3) & 1) * 16);

    float acc[2][8][4];
    #pragma unroll
    for (int mt = 0; mt < 2; mt++)
        #pragma unroll
        for (int nt = 0; nt < 8; nt++)
            #pragma unroll
            for (int q = 0; q < 4; q++) acc[mt][nt][q] = 0.0f;

    // ---- prologue: W(0), W(1) cp.async (two groups); A(0) -> st0; A(1) -> regs ----
    #pragma unroll
    for (int it = 0; it < 4; it++) {
        uint32_t dst = smb + SW0 + (uint32_t)(wrow[it] * 144 + wseg[it] * 16);
        size_t gb = (((size_t)(h_base + wrow[it])) << 10) + (wseg[it] << 4);
        CP_ASYNC16(dst, (const char*)g_Wh + gb);
    }
    CP_COMMIT();
    #pragma unroll
    for (int it = 0; it < 4; it++) {
        uint32_t dst = smb + SW0 + (uint32_t)(WSTG + wrow[it] * 144 + wseg[it] * 16);
        size_t gb = (((size_t)(h_base + wrow[it])) << 10) + (1u << 7) + (wseg[it] << 4);
        CP_ASYNC16(dst, (const char*)g_Wh + gb);
    }
    CP_COMMIT();
    float4 apre[2][2];
    #pragma unroll
    for (int it = 0; it < 2; it++) {
        apre[it][0] = *(const float4*)(aptr[it]);
        apre[it][1] = *(const float4*)(aptr[it] + 4);
    }
    #pragma unroll
    for (int it = 0; it < 2; it++)
        store_a_pair(sm, 0, arow[it], apair[it], apre[it][0], apre[it][1]);
    #pragma unroll
    for (int it = 0; it < 2; it++) {
        apre[it][0] = *(const float4*)(aptr[it] + 64);
        apre[it][1] = *(const float4*)(aptr[it] + 68);
    }

    #pragma unroll
    for (int kc = 0; kc < 8; kc++) {
        const int st = kc & 3;
        // ---- producers (into stages not read until >= 2 barriers from now) ----
        if (kc < 7) {
            #pragma unroll
            for (int it = 0; it < 2; it++)
                store_a_pair(sm, (kc + 1) & 3, arow[it], apair[it], apre[it][0], apre[it][1]);
        }
        if (kc < 6) {
            const int st2 = (kc + 2) & 3;
            #pragma unroll
            for (int it = 0; it < 4; it++) {
                uint32_t dst = smb + SW0 + (uint32_t)(st2 * WSTG + wrow[it] * 144 + wseg[it] * 16);
                size_t gb = (((size_t)(h_base + wrow[it])) << 10) + (((size_t)(kc + 2)) << 7) + (wseg[it] << 4);
                CP_ASYNC16(dst, (const char*)g_Wh + gb);
            }
            CP_COMMIT();
            #pragma unroll
            for (int it = 0; it < 2; it++) {
                apre[it][0] = *(const float4*)(aptr[it] + (kc + 2) * 64);
                apre[it][1] = *(const float4*)(aptr[it] + (kc + 2) * 64 + 4);
            }
        }
        // ---- ensure W(kc) group landed (depth-2: groups kc+1, kc+2 stay in flight) ----
        if (kc < 6)      { CP_WAITG(2); }
        else if (kc == 6){ CP_WAITG(1); }
        else             { CP_WAITG(0); }
        __syncthreads();
        // ---- MMAs on stage st: hoist ALL fragment loads before MMAs (MLP-6 LDSM) ----
        const uint32_t a_st = a_base + (uint32_t)(st * ASTG);
        const uint32_t b_st = b_base + (uint32_t)(st * WSTG);
        #pragma unroll
        for (int kk = 0; kk < 4; kk++) {
            uint32_t A[2][4], Bf[4][4];
            #pragma unroll
            for (int mt = 0; mt < 2; mt++) {
                uint32_t ad = a_st + (uint32_t)(mt * 16 * 144 + kk * 32);
                LDSM4(A[mt][0], A[mt][1], A[mt][2], A[mt][3], ad);
            }
            #pragma unroll
            for (int nn = 0; nn < 4; nn++) {
                uint32_t bd = b_st + (uint32_t)(nn * 16 * 144 + kk * 32);
                LDSM4(Bf[nn][0], Bf[nn][1], Bf[nn][2], Bf[nn][3], bd);
            }
            #pragma unroll
            for (int nn = 0; nn < 4; nn++) {
                #pragma unroll
                for (int mt = 0; mt < 2; mt++) {
                    MMAF16(acc[mt][2 * nn],     A[mt], Bf[nn][0], Bf[nn][1]);
                    MMAF16(acc[mt][2 * nn + 1], A[mt], Bf[nn][2], Bf[nn][3]);
                }
            }
        }
    }

    // ---- epilogue ----
    float pa[4] = {0.f, 0.f, 0.f, 0.f};
    const int hb = warp_h * 64;
    #pragma unroll
    for (int nt = 0; nt < 8; nt++) {
        int h0 = hb + nt * 8 + 2 * (lane & 3);
        float v0 = sv[h0], v1 = sv[h0 + 1];
        float a0 = sadd[h0], a1 = sadd[h0 + 1];
        #pragma unroll
        for (int mt = 0; mt < 2; mt++) {
            #pragma unroll
            for (int rh = 0; rh < 2; rh++) {
                float x0 = acc[mt][nt][rh * 2 + 0] + a0;
                float x1 = acc[mt][nt][rh * 2 + 1] + a1;
                pa[mt * 2 + rh] = fmaf(v0, fast_tanh(x0), pa[mt * 2 + rh]);
                pa[mt * 2 + rh] = fmaf(v1, fast_tanh(x1), pa[mt * 2 + rh]);
            }
        }
    }
    #pragma unroll
    for (int q = 0; q < 4; q++) {
        pa[q] += __shfl_xor_sync(0xffffffffu, pa[q], 1);
        pa[q] += __shfl_xor_sync(0xffffffffu, pa[q], 2);
    }
    __syncthreads();
    if ((lane & 3) == 0) {
        int r = lane >> 2;
        #pragma unroll
        for (int mt = 0; mt < 2; mt++)
            #pragma unroll
            for (int rh = 0; rh < 2; rh++)
                atomicAdd(&satt[warp_s * 32 + mt * 16 + rh * 8 + r], pa[mt * 2 + rh]);
    }
    __syncthreads();
    if (tid < MS) {
        int ii = tile * MS + tid;
        if (ii < cnt) atomicAdd(&g_att[b * S_ + ii], satt[tid]);
    }
}

// ---------------- K2: softmax ----------------
__device__ __forceinline__ float warp_max(float x) {
    #pragma unroll
    for (int o = 16; o; o >>= 1) x = fmaxf(x, __shfl_xor_sync(0xffffffffu, x, o));
    return x;
}
__device__ __forceinline__ float warp_sum(float x) {
    #pragma unroll
    for (int o = 16; o; o >>= 1) x += __shfl_xor_sync(0xffffffffu, x, o);
    return x;
}
__global__ void __launch_bounds__(1024) k2_softmax(float* __restrict__ out_alpha) {
    __shared__ float red[32];
    __shared__ float bc;
    int b = blockIdx.x, tid = threadIdx.x, lane = tid & 31, warp = tid >> 5;
    int cnt = g_cnt[b];
    const float NEG = -1e30f;
    float v[4];
    #pragma unroll
    for (int k = 0; k < 4; k++) {
        int i = tid + k * 1024;
        v[k] = (i < cnt) ? g_att[b * S_ + i] : NEG;
    }
    float m = fmaxf(fmaxf(v[0], v[1]), fmaxf(v[2], v[3]));
    m = warp_max(m);
    if (lane == 0) red[warp] = m;
    __syncthreads();
    if (warp == 0) { float t = warp_max(red[lane]); if (lane == 0) bc = t; }
    __syncthreads();
    m = bc;
    float s = 0.f;
    #pragma unroll
    for (int k = 0; k < 4; k++) s += __expf(v[k] - m);
    s = warp_sum(s);
    __syncthreads();
    if (lane == 0) red[warp] = s;
    __syncthreads();
    if (warp == 0) { float t = warp_sum(red[lane]); if (lane == 0) bc = t; }
    __syncthreads();
    float inv = 1.0f / bc;
    #pragma unroll
    for (int k = 0; k < 4; k++) out_alpha[b * S_ + tid + k * 1024] = 1e-6f;
    __syncthreads();
    #pragma unroll
    for (int k = 0; k < 4; k++) {
        int i = tid + k * 1024;
        if (i < cnt) {
            float al = __expf(v[k] - m) * inv;
            g_alpha[b * S_ + i] = al;
            out_alpha[b * S_ + g_idx[b * S_ + i]] = al + 1e-6f;
        }
    }
}

// ---------------- K3: cbar partials, float4 gather ----------------
__global__ void __launch_bounds__(128) k3_cbar(const float* __restrict__ ctx) {
    int sc = blockIdx.x, b = blockIdx.y;
    int tid = threadIdx.x;
    int d4 = tid * 4;
    __shared__ int   sIx[256];
    __shared__ float sAl[256];
    int cnt = g_cnt[b];
    int s0 = sc * 256, s1 = min(s0 + 256, cnt);
    int n = s1 - s0;
    if (n < 0) n = 0;
    for (int j = tid; j < 256; j += 128) {
        int i = s0 + j;
        sIx[j] = (i < s1) ? g_idx[b * S_ + i] : 0;
        sAl[j] = (i < s1) ? g_alpha[b * S_ + i] : 0.f;
    }
    __syncthreads();
    float4 a0 = {0,0,0,0}, a1 = {0,0,0,0}, a2 = {0,0,0,0}, a3 = {0,0,0,0};
    const size_t bS = (size_t)b * S_;
    int j = 0;
    for (; j + 3 < n; j += 4) {
        float4 c0 = *(const float4*)(ctx + (bS + sIx[j + 0]) * D_ + d4);
        float4 c1 = *(const float4*)(ctx + (bS + sIx[j + 1]) * D_ + d4);
        float4 c2 = *(const float4*)(ctx + (bS + sIx[j + 2]) * D_ + d4);
        float4 c3 = *(const float4*)(ctx + (bS + sIx[j + 3]) * D_ + d4);
        float w0 = sAl[j + 0], w1 = sAl[j + 1], w2 = sAl[j + 2], w3 = sAl[j + 3];
        a0.x = fmaf(w0, c0.x, a0.x); a0.y = fmaf(w0, c0.y, a0.y);
        a0.z = fmaf(w0, c0.z, a0.z); a0.w = fmaf(w0, c0.w, a0.w);
        a1.x = fmaf(w1, c1.x, a1.x); a1.y = fmaf(w1, c1.y, a1.y);
        a1.z = fmaf(w1, c1.z, a1.z); a1.w = fmaf(w1, c1.w, a1.w);
        a2.x = fmaf(w2, c2.x, a2.x); a2.y = fmaf(w2, c2.y, a2.y);
        a2.z = fmaf(w2, c2.z, a2.z); a2.w = fmaf(w2, c2.w, a2.w);
        a3.x = fmaf(w3, c3.x, a3.x); a3.y = fmaf(w3, c3.y, a3.y);
        a3.z = fmaf(w3, c3.z, a3.z); a3.w = fmaf(w3, c3.w, a3.w);
    }
    for (; j < n; j++) {
        float4 c = *(const float4*)(ctx + (bS + sIx[j]) * D_ + d4);
        float w = sAl[j];
        a0.x = fmaf(w, c.x, a0.x); a0.y = fmaf(w, c.y, a0.y);
        a0.z = fmaf(w, c.z, a0.z); a0.w = fmaf(w, c.w, a0.w);
    }
    float4 r;
    r.x = (a0.x + a1.x) + (a2.x + a3.x);
    r.y = (a0.y + a1.y) + (a2.y + a3.y);
    r.z = (a0.z + a1.z) + (a2.z + a3.z);
    r.w = (a0.w + a1.w) + (a2.w + a3.w);
    *(float4*)(g_cbar_part + ((size_t)b * 16 + sc) * D_ + d4) = r;
}

// ---------------- K3b ----------------
__global__ void __launch_bounds__(512) k3b_reduce() {
    int b = blockIdx.x, d = threadIdx.x;
    float acc = 0.f;
    #pragma unroll
    for (int p = 0; p < 16; p++) acc += g_cbar_part[((size_t)b * 16 + p) * D_ + d];
    g_cbar[b * D_ + d] = acc;
}

// ---------------- K4 ----------------
__global__ void __launch_bounds__(256) k4_hidden(const float* __restrict__ W_ctx,
                                                 const float* __restrict__ b_ctx,
                                                 float* __restrict__ out) {
    int gw = blockIdx.x * 8 + (threadIdx.x >> 5);
    int lane = threadIdx.x & 31;
    int b = gw >> 9, h = gw & 511;
    const float* w = W_ctx + (size_t)h * D_;
    const float* cb = g_cbar + (size_t)b * D_;
    float s = 0.f;
    #pragma unroll
    for (int i = 0; i < 16; i++) {
        int d = lane + 32 * i;
        s = fmaf(w[d], cb[d], s);
    }
    #pragma unroll
    for (int o = 16; o; o >>= 1) s += __shfl_xor_sync(0xffffffffu, s, o);
    if (lane == 0) out[b * H_ + h] = s + b_ctx[h];
}

// ---------------- launch ----------------
extern "C" void kernel_launch(void* const* d_in, const int* in_sizes, int n_in,
                              void* d_out, int out_size) {
    const float* input   = (const float*)d_in[0];
    const float* context = (const float*)d_in[1];
    const int*   mask    = (const int*)d_in[2];
    const float* W_in  = (const float*)d_in[3];
    const float* b_in  = (const float*)d_in[4];
    const float* W_ctx = (const float*)d_in[5];
    const float* b_ctx = (const float*)d_in[6];
    const float* V     = (const float*)d_in[7];
    float* out = (float*)d_out;

    cudaFuncSetAttribute(k1_main, cudaFuncAttributeMaxDynamicSharedMemorySize, SMEM_K1);

    k0_fused<<<3104, 256>>>(W_ctx, input, W_in, b_in, b_ctx, mask);
    k1_main<<<dim3(S_ / MS, 2, B_), 512, SMEM_K1>>>(context, V);
    k2_softmax<<<B_, 1024>>>(out + B_ * H_);
    k3_cbar<<<dim3(16, B_), 128>>>(context);
    k3b_reduce<<<B_, 512>>>();
    k4_hidden<<<B_ * H_ / 8, 256>>>(W_ctx, b_ctx, out);
}

// round 13
// speedup vs baseline: 1.4997x; 1.1173x over previous
#include <cuda_runtime.h>
#include <cuda_fp16.h>
#include <cstdint>

#define B_ 32
#define S_ 4096
#define D_ 512
#define H_ 512

// ---------------- device scratch ----------------
__device__ float  g_add[B_ * H_];
__device__ __half g_Wh[H_ * D_];
__device__ float  g_att[B_ * S_];
__device__ float  g_alpha[B_ * S_];
__device__ float  g_cbar_part[B_ * 32 * D_];
__device__ float  g_cbar[B_ * D_];
__device__ int    g_idx[B_ * S_];
__device__ int    g_cnt[B_];

// ---------------- helpers ----------------
__device__ __forceinline__ uint32_t smem_u32(const void* p) {
    uint32_t a;
    asm("{ .reg .u64 t; cvta.to.shared.u64 t, %1; cvt.u32.u64 %0, t; }" : "=r"(a) : "l"(p));
    return a;
}

__device__ __forceinline__ uint32_t h2_as_u32(__half2 h) {
    union { __half2 h; uint32_t u; } cvt;
    cvt.h = h;
    return cvt.u;
}

#define LDSM4(r0, r1, r2, r3, addr) \
    asm volatile("ldmatrix.sync.aligned.m8n8.x4.shared.b16 {%0,%1,%2,%3}, [%4];" \
                 : "=r"(r0), "=r"(r1), "=r"(r2), "=r"(r3) : "r"(addr))

#define MMAF16(d, a, b0, b1) \
    asm volatile("mma.sync.aligned.m16n8k16.row.col.f32.f16.f16.f32 " \
                 "{%0,%1,%2,%3}, {%4,%5,%6,%7}, {%8,%9}, {%0,%1,%2,%3};" \
                 : "+f"((d)[0]), "+f"((d)[1]), "+f"((d)[2]), "+f"((d)[3]) \
                 : "r"((a)[0]), "r"((a)[1]), "r"((a)[2]), "r"((a)[3]), "r"(b0), "r"(b1))

#define CP_ASYNC16(dst, src) \
    asm volatile("cp.async.cg.shared.global [%0], [%1], 16;" :: "r"(dst), "l"(src))
#define CP_COMMIT()  asm volatile("cp.async.commit_group;")
#define CP_WAITG(n)  asm volatile("cp.async.wait_group %0;" :: "n"(n))

// Accurate tanh with NO MUFU. abs err ~1e-5.
__device__ __forceinline__ float fast_tanh(float x) {
    float ax = fabsf(x);
    float z  = fminf(ax * 2.8853900817779268f, 30.0f);
    float zf = z + 12582912.0f;
    int   ni = __float_as_int(zf) - 0x4B400000;
    float fr = z - (zf - 12582912.0f);
    float p  = 1.3333558146e-3f;
    p = fmaf(p, fr, 9.6181291076e-3f);
    p = fmaf(p, fr, 5.5504108665e-2f);
    p = fmaf(p, fr, 2.4022650696e-1f);
    p = fmaf(p, fr, 6.9314718056e-1f);
    p = fmaf(p, fr, 1.0f);
    float u = __int_as_float((ni + 127) << 23) * p;
    float d = u + 1.0f;
    float r = __int_as_float(0x7EF311C3u - __float_as_uint(d));
    r = r * fmaf(-d, r, 2.0f);
    r = r * fmaf(-d, r, 2.0f);
    float t = fmaf(-2.0f, r, 1.0f);
    return copysignf(t, x);
}

// ---------------- K0 fused: W->fp16 | add | compact (independent jobs) ----------------
__global__ void __launch_bounds__(256) k0_fused(const float* __restrict__ W_ctx,
                                                const float* __restrict__ input,
                                                const float* __restrict__ W_in,
                                                const float* __restrict__ b_in,
                                                const float* __restrict__ b_ctx,
                                                const int* __restrict__ mask) {
    int bx = blockIdx.x, tid = threadIdx.x;
    if (bx < 1024) {
        int i = bx * 256 + tid;
        g_Wh[i] = __float2half_rn(W_ctx[i]);
    } else if (bx < 3072) {
        int gw = (bx - 1024) * 8 + (tid >> 5);
        int lane = tid & 31;
        int b = gw >> 9, h = gw & 511;
        const float* w = W_in + (size_t)h * D_;
        const float* in = input + (size_t)b * D_;
        float s = 0.f;
        #pragma unroll
        for (int i = 0; i < 16; i++) {
            int d = lane + 32 * i;
            s = fmaf(w[d], in[d], s);
        }
        #pragma unroll
        for (int o = 16; o; o >>= 1) s += __shfl_xor_sync(0xffffffffu, s, o);
        if (lane == 0) g_add[b * H_ + h] = s + b_in[h] + b_ctx[h];
    } else {
        int b = bx - 3072, lane = tid & 31;
        for (int i = tid; i < S_; i += 256) g_att[b * S_ + i] = 0.f;
        if (tid < 32) {
            int base = 0;
            for (int s0 = 0; s0 < S_; s0 += 32) {
                int s = s0 + lane;
                bool keep = (mask[b * S_ + s] == 0);
                unsigned bal = __ballot_sync(0xffffffffu, keep);
                int rank = __popc(bal & ((1u << lane) - 1u));
                if (keep) g_idx[b * S_ + base + rank] = s;
                base += __popc(bal);
            }
            if (lane == 0) g_cnt[b] = base;
        }
    }
}

// ---------------- K1: fp16 single-term GEMM, 4-stage depth-2 pipeline, hoisted LDSM ----------------
#define MS 128
#define NH 256
#define ASTG 18432
#define WSTG 36864
#define SW0  73728
#define SADD 221184
#define SVV  222208
#define SATT 223232
#define SIDX 223744
#define SMEM_K1 224256

__device__ __forceinline__ void store_a_pair(char* sm, int st, int row, int segpair,
                                             float4 x, float4 y) {
    uint4 v;
    v.x = h2_as_u32(__floats2half2_rn(x.x, x.y));
    v.y = h2_as_u32(__floats2half2_rn(x.z, x.w));
    v.z = h2_as_u32(__floats2half2_rn(y.x, y.y));
    v.w = h2_as_u32(__floats2half2_rn(y.z, y.w));
    *(uint4*)(sm + st * ASTG + row * 144 + segpair * 16) = v;
}

__global__ void __launch_bounds__(512, 1) k1_main(const float* __restrict__ ctx,
                                                  const float* __restrict__ V) {
    extern __shared__ char sm[];
    const int tid = threadIdx.x, lane = tid & 31, wid = tid >> 5;
    const int tile = blockIdx.x, h_half = blockIdx.y, b = blockIdx.z;
    const int cnt = g_cnt[b];
    if (tile * MS >= cnt) return;
    const int h_base = h_half * NH;

    float* sadd = (float*)(sm + SADD);
    float* sv   = (float*)(sm + SVV);
    float* satt = (float*)(sm + SATT);
    int*   sidx = (int*)(sm + SIDX);
    if (tid < NH) { sadd[tid] = g_add[b * H_ + h_base + tid]; sv[tid] = V[h_base + tid]; }
    if (tid < MS) {
        int ii = tile * MS + tid;
        if (ii >= cnt) ii = cnt - 1;
        sidx[tid] = g_idx[b * S_ + ii];
        satt[tid] = 0.0f;
    }
    __syncthreads();

    const uint32_t smb = smem_u32(sm);
    const int warp_s = wid & 3, warp_h = wid >> 2;

    const float* aptr[2];
    int arow[2], apair[2];
    #pragma unroll
    for (int it = 0; it < 2; it++) {
        int p = tid + it * 512;
        arow[it] = p >> 3; apair[it] = p & 7;
        aptr[it] = ctx + ((size_t)(b * S_ + sidx[arow[it]])) * D_ + apair[it] * 8;
    }
    int wrow[4], wseg[4];
    #pragma unroll
    for (int it = 0; it < 4; it++) {
        int u = tid + it * 512;
        wrow[it] = u >> 3; wseg[it] = u & 7;
    }

    const uint32_t a_base = smb + (uint32_t)((warp_s * 32 + (lane & 15)) * 144 + (lane >> 4) * 16);
    const uint32_t b_base = smb + SW0 +
        (uint32_t)((warp_h * 64 + ((lane >> 4) & 1) * 8 + (lane & 7)) * 144 + ((lane >> 3) & 1) * 16);

    float acc[2][8][4];
    #pragma unroll
    for (int mt = 0; mt < 2; mt++)
        #pragma unroll
        for (int nt = 0; nt < 8; nt++)
            #pragma unroll
            for (int q = 0; q < 4; q++) acc[mt][nt][q] = 0.0f;

    #pragma unroll
    for (int it = 0; it < 4; it++) {
        uint32_t dst = smb + SW0 + (uint32_t)(wrow[it] * 144 + wseg[it] * 16);
        size_t gb = (((size_t)(h_base + wrow[it])) << 10) + (wseg[it] << 4);
        CP_ASYNC16(dst, (const char*)g_Wh + gb);
    }
    CP_COMMIT();
    #pragma unroll
    for (int it = 0; it < 4; it++) {
        uint32_t dst = smb + SW0 + (uint32_t)(WSTG + wrow[it] * 144 + wseg[it] * 16);
        size_t gb = (((size_t)(h_base + wrow[it])) << 10) + (1u << 7) + (wseg[it] << 4);
        CP_ASYNC16(dst, (const char*)g_Wh + gb);
    }
    CP_COMMIT();
    float4 apre[2][2];
    #pragma unroll
    for (int it = 0; it < 2; it++) {
        apre[it][0] = *(const float4*)(aptr[it]);
        apre[it][1] = *(const float4*)(aptr[it] + 4);
    }
    #pragma unroll
    for (int it = 0; it < 2; it++)
        store_a_pair(sm, 0, arow[it], apair[it], apre[it][0], apre[it][1]);
    #pragma unroll
    for (int it = 0; it < 2; it++) {
        apre[it][0] = *(const float4*)(aptr[it] + 64);
        apre[it][1] = *(const float4*)(aptr[it] + 68);
    }

    #pragma unroll
    for (int kc = 0; kc < 8; kc++) {
        const int st = kc & 3;
        if (kc < 7) {
            #pragma unroll
            for (int it = 0; it < 2; it++)
                store_a_pair(sm, (kc + 1) & 3, arow[it], apair[it], apre[it][0], apre[it][1]);
        }
        if (kc < 6) {
            const int st2 = (kc + 2) & 3;
            #pragma unroll
            for (int it = 0; it < 4; it++) {
                uint32_t dst = smb + SW0 + (uint32_t)(st2 * WSTG + wrow[it] * 144 + wseg[it] * 16);
                size_t gb = (((size_t)(h_base + wrow[it])) << 10) + (((size_t)(kc + 2)) << 7) + (wseg[it] << 4);
                CP_ASYNC16(dst, (const char*)g_Wh + gb);
            }
            CP_COMMIT();
            #pragma unroll
            for (int it = 0; it < 2; it++) {
                apre[it][0] = *(const float4*)(aptr[it] + (kc + 2) * 64);
                apre[it][1] = *(const float4*)(aptr[it] + (kc + 2) * 64 + 4);
            }
        }
        if (kc < 6)      { CP_WAITG(2); }
        else if (kc == 6){ CP_WAITG(1); }
        else             { CP_WAITG(0); }
        __syncthreads();
        const uint32_t a_st = a_base + (uint32_t)(st * ASTG);
        const uint32_t b_st = b_base + (uint32_t)(st * WSTG);
        #pragma unroll
        for (int kk = 0; kk < 4; kk++) {
            uint32_t A[2][4], Bf[4][4];
            #pragma unroll
            for (int mt = 0; mt < 2; mt++) {
                uint32_t ad = a_st + (uint32_t)(mt * 16 * 144 + kk * 32);
                LDSM4(A[mt][0], A[mt][1], A[mt][2], A[mt][3], ad);
            }
            #pragma unroll
            for (int nn = 0; nn < 4; nn++) {
                uint32_t bd = b_st + (uint32_t)(nn * 16 * 144 + kk * 32);
                LDSM4(Bf[nn][0], Bf[nn][1], Bf[nn][2], Bf[nn][3], bd);
            }
            #pragma unroll
            for (int nn = 0; nn < 4; nn++) {
                #pragma unroll
                for (int mt = 0; mt < 2; mt++) {
                    MMAF16(acc[mt][2 * nn],     A[mt], Bf[nn][0], Bf[nn][1]);
                    MMAF16(acc[mt][2 * nn + 1], A[mt], Bf[nn][2], Bf[nn][3]);
                }
            }
        }
    }

    float pa[4] = {0.f, 0.f, 0.f, 0.f};
    const int hb = warp_h * 64;
    #pragma unroll
    for (int nt = 0; nt < 8; nt++) {
        int h0 = hb + nt * 8 + 2 * (lane & 3);
        float v0 = sv[h0], v1 = sv[h0 + 1];
        float a0 = sadd[h0], a1 = sadd[h0 + 1];
        #pragma unroll
        for (int mt = 0; mt < 2; mt++) {
            #pragma unroll
            for (int rh = 0; rh < 2; rh++) {
                float x0 = acc[mt][nt][rh * 2 + 0] + a0;
                float x1 = acc[mt][nt][rh * 2 + 1] + a1;
                pa[mt * 2 + rh] = fmaf(v0, fast_tanh(x0), pa[mt * 2 + rh]);
                pa[mt * 2 + rh] = fmaf(v1, fast_tanh(x1), pa[mt * 2 + rh]);
            }
        }
    }
    #pragma unroll
    for (int q = 0; q < 4; q++) {
        pa[q] += __shfl_xor_sync(0xffffffffu, pa[q], 1);
        pa[q] += __shfl_xor_sync(0xffffffffu, pa[q], 2);
    }
    __syncthreads();
    if ((lane & 3) == 0) {
        int r = lane >> 2;
        #pragma unroll
        for (int mt = 0; mt < 2; mt++)
            #pragma unroll
            for (int rh = 0; rh < 2; rh++)
                atomicAdd(&satt[warp_s * 32 + mt * 16 + rh * 8 + r], pa[mt * 2 + rh]);
    }
    __syncthreads();
    if (tid < MS) {
        int ii = tile * MS + tid;
        if (ii < cnt) atomicAdd(&g_att[b * S_ + ii], satt[tid]);
    }
}

// ---------------- K2: softmax ----------------
__device__ __forceinline__ float warp_max(float x) {
    #pragma unroll
    for (int o = 16; o; o >>= 1) x = fmaxf(x, __shfl_xor_sync(0xffffffffu, x, o));
    return x;
}
__device__ __forceinline__ float warp_sum(float x) {
    #pragma unroll
    for (int o = 16; o; o >>= 1) x += __shfl_xor_sync(0xffffffffu, x, o);
    return x;
}
__global__ void __launch_bounds__(1024) k2_softmax(float* __restrict__ out_alpha) {
    __shared__ float red[32];
    __shared__ float bc;
    int b = blockIdx.x, tid = threadIdx.x, lane = tid & 31, warp = tid >> 5;
    int cnt = g_cnt[b];
    const float NEG = -1e30f;
    float v[4];
    #pragma unroll
    for (int k = 0; k < 4; k++) {
        int i = tid + k * 1024;
        v[k] = (i < cnt) ? g_att[b * S_ + i] : NEG;
    }
    float m = fmaxf(fmaxf(v[0], v[1]), fmaxf(v[2], v[3]));
    m = warp_max(m);
    if (lane == 0) red[warp] = m;
    __syncthreads();
    if (warp == 0) { float t = warp_max(red[lane]); if (lane == 0) bc = t; }
    __syncthreads();
    m = bc;
    float s = 0.f;
    #pragma unroll
    for (int k = 0; k < 4; k++) s += __expf(v[k] - m);
    s = warp_sum(s);
    __syncthreads();
    if (lane == 0) red[warp] = s;
    __syncthreads();
    if (warp == 0) { float t = warp_sum(red[lane]); if (lane == 0) bc = t; }
    __syncthreads();
    float inv = 1.0f / bc;
    #pragma unroll
    for (int k = 0; k < 4; k++) out_alpha[b * S_ + tid + k * 1024] = 1e-6f;
    __syncthreads();
    #pragma unroll
    for (int k = 0; k < 4; k++) {
        int i = tid + k * 1024;
        if (i < cnt) {
            float al = __expf(v[k] - m) * inv;
            g_alpha[b * S_ + i] = al;
            out_alpha[b * S_ + g_idx[b * S_ + i]] = al + 1e-6f;
        }
    }
}

// ---------------- K3: cbar partials, float4 gather, MLP-8, 1024 CTAs ----------------
__global__ void __launch_bounds__(128) k3_cbar(const float* __restrict__ ctx) {
    int sc = blockIdx.x, b = blockIdx.y;   // 32 s-chunks of 128
    int tid = threadIdx.x;
    int d4 = tid * 4;
    __shared__ int   sIx[128];
    __shared__ float sAl[128];
    int cnt = g_cnt[b];
    int s0 = sc * 128, s1 = min(s0 + 128, cnt);
    int n = s1 - s0;
    if (n < 0) n = 0;
    {
        int i = s0 + tid;
        sIx[tid] = (i < s1) ? g_idx[b * S_ + i] : 0;
        sAl[tid] = (i < s1) ? g_alpha[b * S_ + i] : 0.f;
    }
    __syncthreads();
    float4 a0 = {0,0,0,0}, a1 = {0,0,0,0}, a2 = {0,0,0,0}, a3 = {0,0,0,0};
    float4 a4 = {0,0,0,0}, a5 = {0,0,0,0}, a6 = {0,0,0,0}, a7 = {0,0,0,0};
    const size_t bS = (size_t)b * S_;
    int j = 0;
    for (; j + 7 < n; j += 8) {
        float4 c0 = *(const float4*)(ctx + (bS + sIx[j + 0]) * D_ + d4);
        float4 c1 = *(const float4*)(ctx + (bS + sIx[j + 1]) * D_ + d4);
        float4 c2 = *(const float4*)(ctx + (bS + sIx[j + 2]) * D_ + d4);
        float4 c3 = *(const float4*)(ctx + (bS + sIx[j + 3]) * D_ + d4);
        float4 c4 = *(const float4*)(ctx + (bS + sIx[j + 4]) * D_ + d4);
        float4 c5 = *(const float4*)(ctx + (bS + sIx[j + 5]) * D_ + d4);
        float4 c6 = *(const float4*)(ctx + (bS + sIx[j + 6]) * D_ + d4);
        float4 c7 = *(const float4*)(ctx + (bS + sIx[j + 7]) * D_ + d4);
        float w0 = sAl[j + 0], w1 = sAl[j + 1], w2 = sAl[j + 2], w3 = sAl[j + 3];
        float w4 = sAl[j + 4], w5 = sAl[j + 5], w6 = sAl[j + 6], w7 = sAl[j + 7];
        a0.x = fmaf(w0, c0.x, a0.x); a0.y = fmaf(w0, c0.y, a0.y);
        a0.z = fmaf(w0, c0.z, a0.z); a0.w = fmaf(w0, c0.w, a0.w);
        a1.x = fmaf(w1, c1.x, a1.x); a1.y = fmaf(w1, c1.y, a1.y);
        a1.z = fmaf(w1, c1.z, a1.z); a1.w = fmaf(w1, c1.w, a1.w);
        a2.x = fmaf(w2, c2.x, a2.x); a2.y = fmaf(w2, c2.y, a2.y);
        a2.z = fmaf(w2, c2.z, a2.z); a2.w = fmaf(w2, c2.w, a2.w);
        a3.x = fmaf(w3, c3.x, a3.x); a3.y = fmaf(w3, c3.y, a3.y);
        a3.z = fmaf(w3, c3.z, a3.z); a3.w = fmaf(w3, c3.w, a3.w);
        a4.x = fmaf(w4, c4.x, a4.x); a4.y = fmaf(w4, c4.y, a4.y);
        a4.z = fmaf(w4, c4.z, a4.z); a4.w = fmaf(w4, c4.w, a4.w);
        a5.x = fmaf(w5, c5.x, a5.x); a5.y = fmaf(w5, c5.y, a5.y);
        a5.z = fmaf(w5, c5.z, a5.z); a5.w = fmaf(w5, c5.w, a5.w);
        a6.x = fmaf(w6, c6.x, a6.x); a6.y = fmaf(w6, c6.y, a6.y);
        a6.z = fmaf(w6, c6.z, a6.z); a6.w = fmaf(w6, c6.w, a6.w);
        a7.x = fmaf(w7, c7.x, a7.x); a7.y = fmaf(w7, c7.y, a7.y);
        a7.z = fmaf(w7, c7.z, a7.z); a7.w = fmaf(w7, c7.w, a7.w);
    }
    for (; j < n; j++) {
        float4 c = *(const float4*)(ctx + (bS + sIx[j]) * D_ + d4);
        float w = sAl[j];
        a0.x = fmaf(w, c.x, a0.x); a0.y = fmaf(w, c.y, a0.y);
        a0.z = fmaf(w, c.z, a0.z); a0.w = fmaf(w, c.w, a0.w);
    }
    float4 r;
    r.x = ((a0.x + a1.x) + (a2.x + a3.x)) + ((a4.x + a5.x) + (a6.x + a7.x));
    r.y = ((a0.y + a1.y) + (a2.y + a3.y)) + ((a4.y + a5.y) + (a6.y + a7.y));
    r.z = ((a0.z + a1.z) + (a2.z + a3.z)) + ((a4.z + a5.z) + (a6.z + a7.z));
    r.w = ((a0.w + a1.w) + (a2.w + a3.w)) + ((a4.w + a5.w) + (a6.w + a7.w));
    *(float4*)(g_cbar_part + ((size_t)b * 32 + sc) * D_ + d4) = r;
}

// ---------------- K3b ----------------
__global__ void __launch_bounds__(512) k3b_reduce() {
    int b = blockIdx.x, d = threadIdx.x;
    float acc = 0.f;
    #pragma unroll
    for (int p = 0; p < 32; p++) acc += g_cbar_part[((size_t)b * 32 + p) * D_ + d];
    g_cbar[b * D_ + d] = acc;
}

// ---------------- K4 ----------------
__global__ void __launch_bounds__(256) k4_hidden(const float* __restrict__ W_ctx,
                                                 const float* __restrict__ b_ctx,
                                                 float* __restrict__ out) {
    int gw = blockIdx.x * 8 + (threadIdx.x >> 5);
    int lane = threadIdx.x & 31;
    int b = gw >> 9, h = gw & 511;
    const float* w = W_ctx + (size_t)h * D_;
    const float* cb = g_cbar + (size_t)b * D_;
    float s = 0.f;
    #pragma unroll
    for (int i = 0; i < 16; i++) {
        int d = lane + 32 * i;
        s = fmaf(w[d], cb[d], s);
    }
    #pragma unroll
    for (int o = 16; o; o >>= 1) s += __shfl_xor_sync(0xffffffffu, s, o);
    if (lane == 0) out[b * H_ + h] = s + b_ctx[h];
}

// ---------------- launch ----------------
extern "C" void kernel_launch(void* const* d_in, const int* in_sizes, int n_in,
                              void* d_out, int out_size) {
    const float* input   = (const float*)d_in[0];
    const float* context = (const float*)d_in[1];
    const int*   mask    = (const int*)d_in[2];
    const float* W_in  = (const float*)d_in[3];
    const float* b_in  = (const float*)d_in[4];
    const float* W_ctx = (const float*)d_in[5];
    const float* b_ctx = (const float*)d_in[6];
    const float* V     = (const float*)d_in[7];
    float* out = (float*)d_out;

    cudaFuncSetAttribute(k1_main, cudaFuncAttributeMaxDynamicSharedMemorySize, SMEM_K1);

    k0_fused<<<3104, 256>>>(W_ctx, input, W_in, b_in, b_ctx, mask);
    k1_main<<<dim3(S_ / MS, 2, B_), 512, SMEM_K1>>>(context, V);
    k2_softmax<<<B_, 1024>>>(out + B_ * H_);
    k3_cbar<<<dim3(32, B_), 128>>>(context);
    k3b_reduce<<<B_, 512>>>();
    k4_hidden<<<B_ * H_ / 8, 256>>>(W_ctx, b_ctx, out);
}

// round 14
// speedup vs baseline: 1.5491x; 1.0330x over previous
#include <cuda_runtime.h>
#include <cuda_fp16.h>
#include <cstdint>

#define B_ 32
#define S_ 4096
#define D_ 512
#define H_ 512

// ---------------- device scratch ----------------
__device__ float  g_add[B_ * H_];
__device__ __half g_Wh[H_ * D_];
__device__ float  g_att[B_ * S_];
__device__ float  g_alpha[B_ * S_];
__device__ float  g_cbar_part[B_ * 64 * D_];
__device__ float  g_cbar[B_ * D_];
__device__ int    g_idx[B_ * S_];
__device__ int    g_cnt[B_];

// ---------------- helpers ----------------
__device__ __forceinline__ uint32_t smem_u32(const void* p) {
    uint32_t a;
    asm("{ .reg .u64 t; cvta.to.shared.u64 t, %1; cvt.u32.u64 %0, t; }" : "=r"(a) : "l"(p));
    return a;
}

__device__ __forceinline__ uint32_t h2_as_u32(__half2 h) {
    union { __half2 h; uint32_t u; } cvt;
    cvt.h = h;
    return cvt.u;
}

#define LDSM4(r0, r1, r2, r3, addr) \
    asm volatile("ldmatrix.sync.aligned.m8n8.x4.shared.b16 {%0,%1,%2,%3}, [%4];" \
                 : "=r"(r0), "=r"(r1), "=r"(r2), "=r"(r3) : "r"(addr))

#define MMAF16(d, a, b0, b1) \
    asm volatile("mma.sync.aligned.m16n8k16.row.col.f32.f16.f16.f32 " \
                 "{%0,%1,%2,%3}, {%4,%5,%6,%7}, {%8,%9}, {%0,%1,%2,%3};" \
                 : "+f"((d)[0]), "+f"((d)[1]), "+f"((d)[2]), "+f"((d)[3]) \
                 : "r"((a)[0]), "r"((a)[1]), "r"((a)[2]), "r"((a)[3]), "r"(b0), "r"(b1))

#define CP_ASYNC16(dst, src) \
    asm volatile("cp.async.cg.shared.global [%0], [%1], 16;" :: "r"(dst), "l"(src))
#define CP_COMMIT()  asm volatile("cp.async.commit_group;")
#define CP_WAITG(n)  asm volatile("cp.async.wait_group %0;" :: "n"(n))

// Accurate tanh with NO MUFU. abs err ~1e-5.
__device__ __forceinline__ float fast_tanh(float x) {
    float ax = fabsf(x);
    float z  = fminf(ax * 2.8853900817779268f, 30.0f);
    float zf = z + 12582912.0f;
    int   ni = __float_as_int(zf) - 0x4B400000;
    float fr = z - (zf - 12582912.0f);
    float p  = 1.3333558146e-3f;
    p = fmaf(p, fr, 9.6181291076e-3f);
    p = fmaf(p, fr, 5.5504108665e-2f);
    p = fmaf(p, fr, 2.4022650696e-1f);
    p = fmaf(p, fr, 6.9314718056e-1f);
    p = fmaf(p, fr, 1.0f);
    float u = __int_as_float((ni + 127) << 23) * p;
    float d = u + 1.0f;
    float r = __int_as_float(0x7EF311C3u - __float_as_uint(d));
    r = r * fmaf(-d, r, 2.0f);
    r = r * fmaf(-d, r, 2.0f);
    float t = fmaf(-2.0f, r, 1.0f);
    return copysignf(t, x);
}

// ---------------- K0 fused: W->fp16 | add | compact (independent jobs) ----------------
__global__ void __launch_bounds__(256) k0_fused(const float* __restrict__ W_ctx,
                                                const float* __restrict__ input,
                                                const float* __restrict__ W_in,
                                                const float* __restrict__ b_in,
                                                const float* __restrict__ b_ctx,
                                                const int* __restrict__ mask) {
    int bx = blockIdx.x, tid = threadIdx.x;
    if (bx < 1024) {
        int i = bx * 256 + tid;
        g_Wh[i] = __float2half_rn(W_ctx[i]);
    } else if (bx < 3072) {
        int gw = (bx - 1024) * 8 + (tid >> 5);
        int lane = tid & 31;
        int b = gw >> 9, h = gw & 511;
        const float* w = W_in + (size_t)h * D_;
        const float* in = input + (size_t)b * D_;
        float s = 0.f;
        #pragma unroll
        for (int i = 0; i < 16; i++) {
            int d = lane + 32 * i;
            s = fmaf(w[d], in[d], s);
        }
        #pragma unroll
        for (int o = 16; o; o >>= 1) s += __shfl_xor_sync(0xffffffffu, s, o);
        if (lane == 0) g_add[b * H_ + h] = s + b_in[h] + b_ctx[h];
    } else {
        int b = bx - 3072, lane = tid & 31;
        for (int i = tid; i < S_; i += 256) g_att[b * S_ + i] = 0.f;
        if (tid < 32) {
            int base = 0;
            for (int s0 = 0; s0 < S_; s0 += 32) {
                int s = s0 + lane;
                bool keep = (mask[b * S_ + s] == 0);
                unsigned bal = __ballot_sync(0xffffffffu, keep);
                int rank = __popc(bal & ((1u << lane) - 1u));
                if (keep) g_idx[b * S_ + base + rank] = s;
                base += __popc(bal);
            }
            if (lane == 0) g_cnt[b] = base;
        }
    }
}

// ---------------- K1: fp16 single-term GEMM, 4-stage depth-2 pipeline, hoisted LDSM ----------------
#define MS 128
#define NH 256
#define ASTG 18432
#define WSTG 36864
#define SW0  73728
#define SADD 221184
#define SVV  222208
#define SATT 223232
#define SIDX 223744
#define SMEM_K1 224256

__device__ __forceinline__ void store_a_pair(char* sm, int st, int row, int segpair,
                                             float4 x, float4 y) {
    uint4 v;
    v.x = h2_as_u32(__floats2half2_rn(x.x, x.y));
    v.y = h2_as_u32(__floats2half2_rn(x.z, x.w));
    v.z = h2_as_u32(__floats2half2_rn(y.x, y.y));
    v.w = h2_as_u32(__floats2half2_rn(y.z, y.w));
    *(uint4*)(sm + st * ASTG + row * 144 + segpair * 16) = v;
}

__global__ void __launch_bounds__(512, 1) k1_main(const float* __restrict__ ctx,
                                                  const float* __restrict__ V) {
    extern __shared__ char sm[];
    const int tid = threadIdx.x, lane = tid & 31, wid = tid >> 5;
    const int tile = blockIdx.x, h_half = blockIdx.y, b = blockIdx.z;
    const int cnt = g_cnt[b];
    if (tile * MS >= cnt) return;
    const int h_base = h_half * NH;

    float* sadd = (float*)(sm + SADD);
    float* sv   = (float*)(sm + SVV);
    float* satt = (float*)(sm + SATT);
    int*   sidx = (int*)(sm + SIDX);
    if (tid < NH) { sadd[tid] = g_add[b * H_ + h_base + tid]; sv[tid] = V[h_base + tid]; }
    if (tid < MS) {
        int ii = tile * MS + tid;
        if (ii >= cnt) ii = cnt - 1;
        sidx[tid] = g_idx[b * S_ + ii];
        satt[tid] = 0.0f;
    }
    __syncthreads();

    const uint32_t smb = smem_u32(sm);
    const int warp_s = wid & 3, warp_h = wid >> 2;

    const float* aptr[2];
    int arow[2], apair[2];
    #pragma unroll
    for (int it = 0; it < 2; it++) {
        int p = tid + it * 512;
        arow[it] = p >> 3; apair[it] = p & 7;
        aptr[it] = ctx + ((size_t)(b * S_ + sidx[arow[it]])) * D_ + apair[it] * 8;
    }
    int wrow[4], wseg[4];
    #pragma unroll
    for (int it = 0; it < 4; it++) {
        int u = tid + it * 512;
        wrow[it] = u >> 3; wseg[it] = u & 7;
    }

    const uint32_t a_base = smb + (uint32_t)((warp_s * 32 + (lane & 15)) * 144 + (lane >> 4) * 16);
    const uint32_t b_base = smb + SW0 +
        (uint32_t)((warp_h * 64 + ((lane >> 4) & 1) * 8 + (lane & 7)) * 144 + ((lane >> 3) & 1) * 16);

    float acc[2][8][4];
    #pragma unroll
    for (int mt = 0; mt < 2; mt++)
        #pragma unroll
        for (int nt = 0; nt < 8; nt++)
            #pragma unroll
            for (int q = 0; q < 4; q++) acc[mt][nt][q] = 0.0f;

    #pragma unroll
    for (int it = 0; it < 4; it++) {
        uint32_t dst = smb + SW0 + (uint32_t)(wrow[it] * 144 + wseg[it] * 16);
        size_t gb = (((size_t)(h_base + wrow[it])) << 10) + (wseg[it] << 4);
        CP_ASYNC16(dst, (const char*)g_Wh + gb);
    }
    CP_COMMIT();
    #pragma unroll
    for (int it = 0; it < 4; it++) {
        uint32_t dst = smb + SW0 + (uint32_t)(WSTG + wrow[it] * 144 + wseg[it] * 16);
        size_t gb = (((size_t)(h_base + wrow[it])) << 10) + (1u << 7) + (wseg[it] << 4);
        CP_ASYNC16(dst, (const char*)g_Wh + gb);
    }
    CP_COMMIT();
    float4 apre[2][2];
    #pragma unroll
    for (int it = 0; it < 2; it++) {
        apre[it][0] = *(const float4*)(aptr[it]);
        apre[it][1] = *(const float4*)(aptr[it] + 4);
    }
    #pragma unroll
    for (int it = 0; it < 2; it++)
        store_a_pair(sm, 0, arow[it], apair[it], apre[it][0], apre[it][1]);
    #pragma unroll
    for (int it = 0; it < 2; it++) {
        apre[it][0] = *(const float4*)(aptr[it] + 64);
        apre[it][1] = *(const float4*)(aptr[it] + 68);
    }

    #pragma unroll
    for (int kc = 0; kc < 8; kc++) {
        const int st = kc & 3;
        if (kc < 7) {
            #pragma unroll
            for (int it = 0; it < 2; it++)
                store_a_pair(sm, (kc + 1) & 3, arow[it], apair[it], apre[it][0], apre[it][1]);
        }
        if (kc < 6) {
            const int st2 = (kc + 2) & 3;
            #pragma unroll
            for (int it = 0; it < 4; it++) {
                uint32_t dst = smb + SW0 + (uint32_t)(st2 * WSTG + wrow[it] * 144 + wseg[it] * 16);
                size_t gb = (((size_t)(h_base + wrow[it])) << 10) + (((size_t)(kc + 2)) << 7) + (wseg[it] << 4);
                CP_ASYNC16(dst, (const char*)g_Wh + gb);
            }
            CP_COMMIT();
            #pragma unroll
            for (int it = 0; it < 2; it++) {
                apre[it][0] = *(const float4*)(aptr[it] + (kc + 2) * 64);
                apre[it][1] = *(const float4*)(aptr[it] + (kc + 2) * 64 + 4);
            }
        }
        if (kc < 6)      { CP_WAITG(2); }
        else if (kc == 6){ CP_WAITG(1); }
        else             { CP_WAITG(0); }
        __syncthreads();
        const uint32_t a_st = a_base + (uint32_t)(st * ASTG);
        const uint32_t b_st = b_base + (uint32_t)(st * WSTG);
        #pragma unroll
        for (int kk = 0; kk < 4; kk++) {
            uint32_t A[2][4], Bf[4][4];
            #pragma unroll
            for (int mt = 0; mt < 2; mt++) {
                uint32_t ad = a_st + (uint32_t)(mt * 16 * 144 + kk * 32);
                LDSM4(A[mt][0], A[mt][1], A[mt][2], A[mt][3], ad);
            }
            #pragma unroll
            for (int nn = 0; nn < 4; nn++) {
                uint32_t bd = b_st + (uint32_t)(nn * 16 * 144 + kk * 32);
                LDSM4(Bf[nn][0], Bf[nn][1], Bf[nn][2], Bf[nn][3], bd);
            }
            #pragma unroll
            for (int nn = 0; nn < 4; nn++) {
                #pragma unroll
                for (int mt = 0; mt < 2; mt++) {
                    MMAF16(acc[mt][2 * nn],     A[mt], Bf[nn][0], Bf[nn][1]);
                    MMAF16(acc[mt][2 * nn + 1], A[mt], Bf[nn][2], Bf[nn][3]);
                }
            }
        }
    }

    float pa[4] = {0.f, 0.f, 0.f, 0.f};
    const int hb = warp_h * 64;
    #pragma unroll
    for (int nt = 0; nt < 8; nt++) {
        int h0 = hb + nt * 8 + 2 * (lane & 3);
        float v0 = sv[h0], v1 = sv[h0 + 1];
        float a0 = sadd[h0], a1 = sadd[h0 + 1];
        #pragma unroll
        for (int mt = 0; mt < 2; mt++) {
            #pragma unroll
            for (int rh = 0; rh < 2; rh++) {
                float x0 = acc[mt][nt][rh * 2 + 0] + a0;
                float x1 = acc[mt][nt][rh * 2 + 1] + a1;
                pa[mt * 2 + rh] = fmaf(v0, fast_tanh(x0), pa[mt * 2 + rh]);
                pa[mt * 2 + rh] = fmaf(v1, fast_tanh(x1), pa[mt * 2 + rh]);
            }
        }
    }
    #pragma unroll
    for (int q = 0; q < 4; q++) {
        pa[q] += __shfl_xor_sync(0xffffffffu, pa[q], 1);
        pa[q] += __shfl_xor_sync(0xffffffffu, pa[q], 2);
    }
    __syncthreads();
    if ((lane & 3) == 0) {
        int r = lane >> 2;
        #pragma unroll
        for (int mt = 0; mt < 2; mt++)
            #pragma unroll
            for (int rh = 0; rh < 2; rh++)
                atomicAdd(&satt[warp_s * 32 + mt * 16 + rh * 8 + r], pa[mt * 2 + rh]);
    }
    __syncthreads();
    if (tid < MS) {
        int ii = tile * MS + tid;
        if (ii < cnt) atomicAdd(&g_att[b * S_ + ii], satt[tid]);
    }
}

// ---------------- K2: softmax ----------------
__device__ __forceinline__ float warp_max(float x) {
    #pragma unroll
    for (int o = 16; o; o >>= 1) x = fmaxf(x, __shfl_xor_sync(0xffffffffu, x, o));
    return x;
}
__device__ __forceinline__ float warp_sum(float x) {
    #pragma unroll
    for (int o = 16; o; o >>= 1) x += __shfl_xor_sync(0xffffffffu, x, o);
    return x;
}
__global__ void __launch_bounds__(1024) k2_softmax(float* __restrict__ out_alpha) {
    __shared__ float red[32];
    __shared__ float bc;
    int b = blockIdx.x, tid = threadIdx.x, lane = tid & 31, warp = tid >> 5;
    int cnt = g_cnt[b];
    const float NEG = -1e30f;
    float v[4];
    #pragma unroll
    for (int k = 0; k < 4; k++) {
        int i = tid + k * 1024;
        v[k] = (i < cnt) ? g_att[b * S_ + i] : NEG;
    }
    float m = fmaxf(fmaxf(v[0], v[1]), fmaxf(v[2], v[3]));
    m = warp_max(m);
    if (lane == 0) red[warp] = m;
    __syncthreads();
    if (warp == 0) { float t = warp_max(red[lane]); if (lane == 0) bc = t; }
    __syncthreads();
    m = bc;
    float s = 0.f;
    #pragma unroll
    for (int k = 0; k < 4; k++) s += __expf(v[k] - m);
    s = warp_sum(s);
    __syncthreads();
    if (lane == 0) red[warp] = s;
    __syncthreads();
    if (warp == 0) { float t = warp_sum(red[lane]); if (lane == 0) bc = t; }
    __syncthreads();
    float inv = 1.0f / bc;
    #pragma unroll
    for (int k = 0; k < 4; k++) out_alpha[b * S_ + tid + k * 1024] = 1e-6f;
    __syncthreads();
    #pragma unroll
    for (int k = 0; k < 4; k++) {
        int i = tid + k * 1024;
        if (i < cnt) {
            float al = __expf(v[k] - m) * inv;
            g_alpha[b * S_ + i] = al;
            out_alpha[b * S_ + g_idx[b * S_ + i]] = al + 1e-6f;
        }
    }
}

// ---------------- K3: cbar partials, float4 gather, MLP-8, 2048 CTAs ----------------
__global__ void __launch_bounds__(128) k3_cbar(const float* __restrict__ ctx) {
    int sc = blockIdx.x, b = blockIdx.y;   // 64 s-chunks of 64
    int tid = threadIdx.x;
    int d4 = tid * 4;
    __shared__ int   sIx[64];
    __shared__ float sAl[64];
    int cnt = g_cnt[b];
    int s0 = sc * 64, s1 = min(s0 + 64, cnt);
    int n = s1 - s0;
    if (n < 0) n = 0;
    if (tid < 64) {
        int i = s0 + tid;
        sIx[tid] = (i < s1) ? g_idx[b * S_ + i] : 0;
        sAl[tid] = (i < s1) ? g_alpha[b * S_ + i] : 0.f;
    }
    __syncthreads();
    float4 a0 = {0,0,0,0}, a1 = {0,0,0,0}, a2 = {0,0,0,0}, a3 = {0,0,0,0};
    float4 a4 = {0,0,0,0}, a5 = {0,0,0,0}, a6 = {0,0,0,0}, a7 = {0,0,0,0};
    const size_t bS = (size_t)b * S_;
    int j = 0;
    for (; j + 7 < n; j += 8) {
        float4 c0 = *(const float4*)(ctx + (bS + sIx[j + 0]) * D_ + d4);
        float4 c1 = *(const float4*)(ctx + (bS + sIx[j + 1]) * D_ + d4);
        float4 c2 = *(const float4*)(ctx + (bS + sIx[j + 2]) * D_ + d4);
        float4 c3 = *(const float4*)(ctx + (bS + sIx[j + 3]) * D_ + d4);
        float4 c4 = *(const float4*)(ctx + (bS + sIx[j + 4]) * D_ + d4);
        float4 c5 = *(const float4*)(ctx + (bS + sIx[j + 5]) * D_ + d4);
        float4 c6 = *(const float4*)(ctx + (bS + sIx[j + 6]) * D_ + d4);
        float4 c7 = *(const float4*)(ctx + (bS + sIx[j + 7]) * D_ + d4);
        float w0 = sAl[j + 0], w1 = sAl[j + 1], w2 = sAl[j + 2], w3 = sAl[j + 3];
        float w4 = sAl[j + 4], w5 = sAl[j + 5], w6 = sAl[j + 6], w7 = sAl[j + 7];
        a0.x = fmaf(w0, c0.x, a0.x); a0.y = fmaf(w0, c0.y, a0.y);
        a0.z = fmaf(w0, c0.z, a0.z); a0.w = fmaf(w0, c0.w, a0.w);
        a1.x = fmaf(w1, c1.x, a1.x); a1.y = fmaf(w1, c1.y, a1.y);
        a1.z = fmaf(w1, c1.z, a1.z); a1.w = fmaf(w1, c1.w, a1.w);
        a2.x = fmaf(w2, c2.x, a2.x); a2.y = fmaf(w2, c2.y, a2.y);
        a2.z = fmaf(w2, c2.z, a2.z); a2.w = fmaf(w2, c2.w, a2.w);
        a3.x = fmaf(w3, c3.x, a3.x); a3.y = fmaf(w3, c3.y, a3.y);
        a3.z = fmaf(w3, c3.z, a3.z); a3.w = fmaf(w3, c3.w, a3.w);
        a4.x = fmaf(w4, c4.x, a4.x); a4.y = fmaf(w4, c4.y, a4.y);
        a4.z = fmaf(w4, c4.z, a4.z); a4.w = fmaf(w4, c4.w, a4.w);
        a5.x = fmaf(w5, c5.x, a5.x); a5.y = fmaf(w5, c5.y, a5.y);
        a5.z = fmaf(w5, c5.z, a5.z); a5.w = fmaf(w5, c5.w, a5.w);
        a6.x = fmaf(w6, c6.x, a6.x); a6.y = fmaf(w6, c6.y, a6.y);
        a6.z = fmaf(w6, c6.z, a6.z); a6.w = fmaf(w6, c6.w, a6.w);
        a7.x = fmaf(w7, c7.x, a7.x); a7.y = fmaf(w7, c7.y, a7.y);
        a7.z = fmaf(w7, c7.z, a7.z); a7.w = fmaf(w7, c7.w, a7.w);
    }
    for (; j < n; j++) {
        float4 c = *(const float4*)(ctx + (bS + sIx[j]) * D_ + d4);
        float w = sAl[j];
        a0.x = fmaf(w, c.x, a0.x); a0.y = fmaf(w, c.y, a0.y);
        a0.z = fmaf(w, c.z, a0.z); a0.w = fmaf(w, c.w, a0.w);
    }
    float4 r;
    r.x = ((a0.x + a1.x) + (a2.x + a3.x)) + ((a4.x + a5.x) + (a6.x + a7.x));
    r.y = ((a0.y + a1.y) + (a2.y + a3.y)) + ((a4.y + a5.y) + (a6.y + a7.y));
    r.z = ((a0.z + a1.z) + (a2.z + a3.z)) + ((a4.z + a5.z) + (a6.z + a7.z));
    r.w = ((a0.w + a1.w) + (a2.w + a3.w)) + ((a4.w + a5.w) + (a6.w + a7.w));
    *(float4*)(g_cbar_part + ((size_t)b * 64 + sc) * D_ + d4) = r;
}

// ---------------- K3b ----------------
__global__ void __launch_bounds__(512) k3b_reduce() {
    int b = blockIdx.x, d = threadIdx.x;
    float acc = 0.f;
    #pragma unroll
    for (int p = 0; p < 64; p++) acc += g_cbar_part[((size_t)b * 64 + p) * D_ + d];
    g_cbar[b * D_ + d] = acc;
}

// ---------------- K4 ----------------
__global__ void __launch_bounds__(256) k4_hidden(const float* __restrict__ W_ctx,
                                                 const float* __restrict__ b_ctx,
                                                 float* __restrict__ out) {
    int gw = blockIdx.x * 8 + (threadIdx.x >> 5);
    int lane = threadIdx.x & 31;
    int b = gw >> 9, h = gw & 511;
    const float* w = W_ctx + (size_t)h * D_;
    const float* cb = g_cbar + (size_t)b * D_;
    float s = 0.f;
    #pragma unroll
    for (int i = 0; i < 16; i++) {
        int d = lane + 32 * i;
        s = fmaf(w[d], cb[d], s);
    }
    #pragma unroll
    for (int o = 16; o; o >>= 1) s += __shfl_xor_sync(0xffffffffu, s, o);
    if (lane == 0) out[b * H_ + h] = s + b_ctx[h];
}

// ---------------- launch ----------------
extern "C" void kernel_launch(void* const* d_in, const int* in_sizes, int n_in,
                              void* d_out, int out_size) {
    const float* input   = (const float*)d_in[0];
    const float* context = (const float*)d_in[1];
    const int*   mask    = (const int*)d_in[2];
    const float* W_in  = (const float*)d_in[3];
    const float* b_in  = (const float*)d_in[4];
    const float* W_ctx = (const float*)d_in[5];
    const float* b_ctx = (const float*)d_in[6];
    const float* V     = (const float*)d_in[7];
    float* out = (float*)d_out;

    cudaFuncSetAttribute(k1_main, cudaFuncAttributeMaxDynamicSharedMemorySize, SMEM_K1);

    k0_fused<<<3104, 256>>>(W_ctx, input, W_in, b_in, b_ctx, mask);
    k1_main<<<dim3(S_ / MS, 2, B_), 512, SMEM_K1>>>(context, V);
    k2_softmax<<<B_, 1024>>>(out + B_ * H_);
    k3_cbar<<<dim3(64, B_), 128>>>(context);
    k3b_reduce<<<B_, 512>>>();
    k4_hidden<<<B_ * H_ / 8, 256>>>(W_ctx, b_ctx, out);
}